// round 8
// baseline (speedup 1.0000x reference)
#include <cuda_runtime.h>
#include <cstdint>
#include <cstddef>

typedef unsigned long long ull;

// ---------------- problem constants ----------------
#define STEPS 100
#define BATCH 64
#define NSPK  (STEPS*BATCH*3*32*32)   // 19,660,800
#define XSZ   (BATCH*3*32*32)         // 196,608
#define N1    (BATCH*32*14*14)        // 401,408  (layer-1 neurons per step)
#define N2    (BATCH*64*5*5)          // 102,400  (layer-2 neurons per step)
#define TB    (STEPS*BATCH)           // 6400

// ---------------- scratch (device globals; no cudaMalloc allowed) ----------
__device__ __align__(16) unsigned char g_spk0[NSPK];          // poisson spikes [t][b][c][h][w]
__device__ __align__(16) float g_curin[(size_t)STEPS*N1];     // [t][b][sp196][oc32]
__device__ unsigned int  g_spk1[(size_t)STEPS*BATCH*196];     // [t][b*196+sp] -> 32-bit oc mask
__device__ __align__(16) float g_curh1[(size_t)STEPS*N2];     // [t][b][oc64*25+sp]
__device__ __align__(16) unsigned char g_spkh1[(size_t)STEPS*N2];
__device__ float         g_fc[STEPS*BATCH*10];
__device__ __align__(16) float g_Wp1[3*36*32];                // pooled conv1 W [c][uv6x6][oc32]
__device__ __align__(16) float g_Wp2[32*36*64];               // pooled conv2 W [c][uv6x6][oc64]

// ---------------- packed f32x2 helpers (bit-exact fp32 pairs) --------------
__device__ __forceinline__ void ffma2(ull& d, ull a, ull b) {
    asm("fma.rn.f32x2 %0, %1, %2, %0;" : "+l"(d) : "l"(a), "l"(b));
}
__device__ __forceinline__ void fadd2(ull& d, ull a) {
    asm("add.rn.f32x2 %0, %0, %1;" : "+l"(d) : "l"(a));
}
__device__ __forceinline__ ull pack_dup(float f) {
    ull p; asm("mov.b64 %0, {%1, %1};" : "=l"(p) : "f"(f)); return p;
}
__device__ __forceinline__ void unpack2(ull p, float& lo, float& hi) {
    asm("mov.b64 {%0, %1}, %2;" : "=f"(lo), "=f"(hi) : "l"(p));
}

// ---------------- cp.async helpers ----------------
__device__ __forceinline__ void cp16(void* dst_smem, const void* src) {
    unsigned d = (unsigned)__cvta_generic_to_shared(dst_smem);
    asm volatile("cp.async.ca.shared.global [%0], [%1], 16;" :: "r"(d), "l"(src));
}
__device__ __forceinline__ void cp_commit() {
    asm volatile("cp.async.commit_group;");
}
template <int N>
__device__ __forceinline__ void cp_wait() {
    asm volatile("cp.async.wait_group %0;" :: "n"(N));
}

// ---------------- threefry2x32 (JAX-exact, partitionable path) -------------
__device__ __forceinline__ uint2 threefry2x32(uint32_t k0, uint32_t k1,
                                              uint32_t x0, uint32_t x1) {
    uint32_t ks0 = k0, ks1 = k1, ks2 = k0 ^ k1 ^ 0x1BD11BDAu;
    x0 += ks0; x1 += ks1;
#define TFR(r) { x0 += x1; x1 = (x1 << (r)) | (x1 >> (32 - (r))); x1 ^= x0; }
    TFR(13) TFR(15) TFR(26) TFR(6)
    x0 += ks1; x1 += ks2 + 1u;
    TFR(17) TFR(29) TFR(16) TFR(24)
    x0 += ks2; x1 += ks0 + 2u;
    TFR(13) TFR(15) TFR(26) TFR(6)
    x0 += ks0; x1 += ks1 + 3u;
    TFR(17) TFR(29) TFR(16) TFR(24)
    x0 += ks1; x1 += ks2 + 4u;
    TFR(13) TFR(15) TFR(26) TFR(6)
    x0 += ks2; x1 += ks0 + 5u;
#undef TFR
    return make_uint2(x0, x1);
}

// ---------------- k0: fold avgpool(2x2,*0.25) into conv weights ------------
__global__ void k_fold(const float* __restrict__ Win, const float* __restrict__ Wh1) {
    int i = blockIdx.x * blockDim.x + threadIdx.x;
    if (i < 3*36*32) {
        int oc = i & 31; int r = i >> 5; int uv = r % 36; int c = r / 36;
        int u = uv / 6, v = uv % 6;
        float s = 0.f;
        #pragma unroll
        for (int dh = 0; dh < 2; dh++)
            #pragma unroll
            for (int dw = 0; dw < 2; dw++) {
                int kh = u - dh, kw = v - dw;
                if (kh >= 0 && kh < 5 && kw >= 0 && kw < 5)
                    s += Win[(oc*3 + c)*25 + kh*5 + kw];
            }
        g_Wp1[i] = 0.25f * s;
    }
    if (i < 32*36*64) {
        int oc = i & 63; int r = i >> 6; int uv = r % 36; int c = r / 36;
        int u = uv / 6, v = uv % 6;
        float s = 0.f;
        #pragma unroll
        for (int dh = 0; dh < 2; dh++)
            #pragma unroll
            for (int dw = 0; dw < 2; dw++) {
                int kh = u - dh, kw = v - dw;
                if (kh >= 0 && kh < 5 && kw >= 0 && kw < 5)
                    s += Wh1[(oc*32 + c)*25 + kh*5 + kw];
            }
        g_Wp2[i] = 0.25f * s;
    }
}

// ---------------- k1: poisson spikes, ILP-4 --------------------------------
__global__ void k_spikes(const float* __restrict__ x) {
    int q = blockIdx.x * 256 + threadIdx.x;      // quad index < NSPK/4
    int i0 = q << 2;
    const float4 xv = *(const float4*)&x[i0 % XSZ];   // XSZ % 4 == 0: no wrap
    uint2 r0 = threefry2x32(0u, 1u, 0u, (uint32_t)(i0 + 0));
    uint2 r1 = threefry2x32(0u, 1u, 0u, (uint32_t)(i0 + 1));
    uint2 r2 = threefry2x32(0u, 1u, 0u, (uint32_t)(i0 + 2));
    uint2 r3 = threefry2x32(0u, 1u, 0u, (uint32_t)(i0 + 3));
    uchar4 o;
    float u;
    u = __uint_as_float(((r0.x ^ r0.y) >> 9) | 0x3f800000u) - 1.0f; o.x = (u < xv.x * 2.0f);
    u = __uint_as_float(((r1.x ^ r1.y) >> 9) | 0x3f800000u) - 1.0f; o.y = (u < xv.y * 2.0f);
    u = __uint_as_float(((r2.x ^ r2.y) >> 9) | 0x3f800000u) - 1.0f; o.z = (u < xv.z * 2.0f);
    u = __uint_as_float(((r3.x ^ r3.y) >> 9) | 0x3f800000u) - 1.0f; o.w = (u < xv.w * 2.0f);
    ((uchar4*)g_spk0)[q] = o;
}

// ---------------- conv1 compute core (shared by both tiles) ----------------
__device__ __forceinline__ void conv1_compute(const float* __restrict__ sIn,
                                              const float* __restrict__ sW,
                                              int tb, int oh, int sp0, int ia) {
    ull accA[8], accB[8];
    #pragma unroll
    for (int j = 0; j < 8; j++) { accA[j] = 0ull; accB[j] = 0ull; }

    #pragma unroll 1
    for (int c = 0; c < 3; c++) {
        const float* sIc = &sIn[c*1024 + ia];
        const float* wc  = &sW[c*1152 + oh*16];
        #pragma unroll 1
        for (int u = 0; u < 6; u++) {
            #pragma unroll
            for (int v = 0; v < 6; v++) {
                ull sa = pack_dup(sIc[u*32 + v]);
                ull sb = pack_dup(sIc[u*32 + v + 2]);
                const ull* w = (const ull*)&wc[(u*6 + v)*32];
                #pragma unroll
                for (int j = 0; j < 8; j++) {
                    ull wj = w[j];
                    ffma2(accA[j], wj, sa);
                    ffma2(accB[j], wj, sb);
                }
            }
        }
    }
    ull* oA = (ull*)&g_curin[(size_t)tb*6272 + sp0*32 + oh*16];
    ull* oB = (ull*)&g_curin[(size_t)tb*6272 + (sp0+1)*32 + oh*16];
    #pragma unroll
    for (int j = 0; j < 8; j++) { oA[j] = accA[j]; oB[j] = accB[j]; }
}

// ---------------- k2: conv1+pool, 2 (t,b) tiles per block ------------------
// weights staged once per block; tile1 input LDG overlapped with tile0 compute
__global__ __launch_bounds__(224) void k_conv1(void) {
    __shared__ float sIn[2][3*32*32];
    __shared__ __align__(16) float sW[3*36*32];
    int tid = threadIdx.x;
    int tb0 = blockIdx.x * 2;

    const uchar4* in0 = (const uchar4*)(g_spk0 + (size_t)tb0 * 3072);
    for (int i = tid; i < 768; i += 224) {
        uchar4 b4 = in0[i];
        *(float4*)&sIn[0][i*4] =
            make_float4((float)b4.x, (float)b4.y, (float)b4.z, (float)b4.w);
    }
    for (int i = tid; i < 3456; i += 224) sW[i] = g_Wp1[i];
    __syncthreads();

    // prefetch tile-1 input into registers (latency overlapped with compute0)
    uchar4 r1[4];
    {
        const uchar4* in1 = (const uchar4*)(g_spk0 + (size_t)(tb0 + 1) * 3072);
        int n = 0;
        for (int i = tid; i < 768; i += 224) r1[n++] = in1[i];
    }

    bool work = tid < 196;
    int oh = 0, sp0 = 0, ia = 0;
    if (work) {
        oh  = tid / 98;               // oc half
        int spi = tid - oh*98;
        sp0 = 2*spi;
        int ph = sp0 / 14, pw = sp0 % 14;
        ia = ph*64 + pw*2;
    }

    if (work) conv1_compute(sIn[0], sW, tb0, oh, sp0, ia);

    {   // store prefetched tile-1 (into other buffer; no sync needed before)
        int n = 0;
        for (int i = tid; i < 768; i += 224) {
            uchar4 b4 = r1[n++];
            *(float4*)&sIn[1][i*4] =
                make_float4((float)b4.x, (float)b4.y, (float)b4.z, (float)b4.w);
        }
    }
    __syncthreads();
    if (work) conv1_compute(sIn[1], sW, tb0 + 1, oh, sp0, ia);
}

// ---------------- k3: LIF scan layer 1 -> ballot bitmasks ------------------
__global__ void k_lif1(void) {
    int n = blockIdx.x*256 + threadIdx.x;       // < 401408 ; n = (b*196+sp)*32+oc
    int lane = threadIdx.x & 31;
    int bs = n >> 5;                            // b*196 + sp
    const float* cur = g_curin + n;
    unsigned* out = g_spk1 + bs;
    float spk = 0.f;
    #pragma unroll 1
    for (int t = 0; t < STEPS; t += 4) {
        float c0 = cur[(size_t)(t+0)*N1];
        float c1 = cur[(size_t)(t+1)*N1];
        float c2 = cur[(size_t)(t+2)*N1];
        float c3 = cur[(size_t)(t+3)*N1];
        float mem; unsigned m0, m1, m2, m3;
        mem = c0 - spk; spk = (mem > 1.f) ? 1.f : 0.f; m0 = __ballot_sync(0xffffffffu, mem > 1.f);
        mem = c1 - spk; spk = (mem > 1.f) ? 1.f : 0.f; m1 = __ballot_sync(0xffffffffu, mem > 1.f);
        mem = c2 - spk; spk = (mem > 1.f) ? 1.f : 0.f; m2 = __ballot_sync(0xffffffffu, mem > 1.f);
        mem = c3 - spk; spk = (mem > 1.f) ? 1.f : 0.f; m3 = __ballot_sync(0xffffffffu, mem > 1.f);
        if (lane == 0) {
            out[(size_t)(t+0)*12544] = m0;
            out[(size_t)(t+1)*12544] = m1;
            out[(size_t)(t+2)*12544] = m2;
            out[(size_t)(t+3)*12544] = m3;
        }
    }
}

// ---------------- k4: conv2+pool, sparse gather + cp.async double buffer ---
// block = (t-group of 4, b); weights for channel c+1 prefetched during c.
__global__ __launch_bounds__(256) void k_conv2(void) {
    __shared__ __align__(16) float sW[2][36*64]; // double-buffered per-channel weights
    __shared__ unsigned sMask4[4*196];           // oc-masks for 4 t
    __shared__ unsigned sRow[4][32*14];          // per-t per-channel row masks

    int tid = threadIdx.x;
    int b   = blockIdx.x & 63;
    int tg  = blockIdx.x >> 6;                  // 0..24
    int t0  = tg * 4;

    for (int i = tid; i < 4*196; i += 256) {
        int tt = i / 196, sp = i - tt*196;
        sMask4[i] = g_spk1[(size_t)(t0 + tt)*12544 + b*196 + sp];
    }
    // prefetch channel-0 weights while masks land / transpose runs
    for (int i = tid; i < 576; i += 256)
        cp16(&sW[0][i*4], &g_Wp2[i*4]);
    cp_commit();
    __syncthreads();
    if (tid < 224) {                            // transpose to row bitmasks
        int c = tid & 31; int rp = tid >> 5;    // rp 0..6
        #pragma unroll
        for (int tt = 0; tt < 4; tt++) {
            const unsigned* mk = &sMask4[tt*196];
            #pragma unroll
            for (int rr = 0; rr < 2; rr++) {
                int ih = rp*2 + rr;
                unsigned m = 0;
                #pragma unroll
                for (int iw = 0; iw < 14; iw++)
                    m |= ((mk[ih*14 + iw] >> c) & 1u) << iw;
                sRow[tt][c*14 + ih] = m;
            }
        }
    }

    int active = (tid < 200);
    int sp = tid >> 3, og = tid & 7;            // sp 0..24, oc octet og*8..+7
    int ph = sp / 5, pw = sp % 5;
    int shift = 2*pw;
    ull acc[4][4];
    #pragma unroll
    for (int tt = 0; tt < 4; tt++)
        #pragma unroll
        for (int j = 0; j < 4; j++) acc[tt][j] = 0ull;

    #pragma unroll 1
    for (int c = 0; c < 32; c++) {
        cp_wait<0>();                           // my copies for channel c done
        __syncthreads();                        // all copies visible; prev gather done
        if (c + 1 < 32) {                       // prefetch c+1 into other buffer
            const float* src = &g_Wp2[(c+1)*2304];
            float* dst = sW[(c+1) & 1];
            for (int i = tid; i < 576; i += 256)
                cp16(&dst[i*4], &src[i*4]);
            cp_commit();
        }
        const float* wbuf = sW[c & 1];
        if (active) {
            #pragma unroll
            for (int tt = 0; tt < 4; tt++) {
                const unsigned* rc = &sRow[tt][c*14 + 2*ph];
                #pragma unroll
                for (int u = 0; u < 6; u++) {
                    unsigned bits = (rc[u] >> shift) & 63u;
                    while (bits) {
                        int v = __ffs(bits) - 1; bits &= bits - 1;
                        const ull* w = (const ull*)&wbuf[(u*6 + v)*64 + og*8];
                        fadd2(acc[tt][0], w[0]); fadd2(acc[tt][1], w[1]);
                        fadd2(acc[tt][2], w[2]); fadd2(acc[tt][3], w[3]);
                    }
                }
            }
        }
        __syncthreads();                        // gather(c) done before buffer c&1 reused
    }

    if (active) {
        #pragma unroll
        for (int tt = 0; tt < 4; tt++) {
            size_t ob = (size_t)((t0 + tt)*64 + b)*1600 + (size_t)(og*8)*25 + sp;
            float f[8];
            unpack2(acc[tt][0], f[0], f[1]); unpack2(acc[tt][1], f[2], f[3]);
            unpack2(acc[tt][2], f[4], f[5]); unpack2(acc[tt][3], f[6], f[7]);
            #pragma unroll
            for (int j = 0; j < 8; j++) g_curh1[ob + j*25] = f[j];
        }
    }
}

// ---------------- k5: LIF scan layer 2 (float4, unroll2) -------------------
__global__ void k_lif2(void) {
    int q = blockIdx.x*256 + threadIdx.x;       // < 25600 float4-neurons
    const float4* cur = (const float4*)g_curh1;
    uchar4* out = (uchar4*)g_spkh1;
    float s0 = 0.f, s1 = 0.f, s2 = 0.f, s3 = 0.f;
    #pragma unroll 1
    for (int t = 0; t < STEPS; t += 2) {
        float4 a = cur[(size_t)(t+0)*25600 + q];
        float4 b = cur[(size_t)(t+1)*25600 + q];
        float m; uchar4 o;
        m = a.x - s0; s0 = (m > 1.f) ? 1.f : 0.f; o.x = (unsigned char)(m > 1.f);
        m = a.y - s1; s1 = (m > 1.f) ? 1.f : 0.f; o.y = (unsigned char)(m > 1.f);
        m = a.z - s2; s2 = (m > 1.f) ? 1.f : 0.f; o.z = (unsigned char)(m > 1.f);
        m = a.w - s3; s3 = (m > 1.f) ? 1.f : 0.f; o.w = (unsigned char)(m > 1.f);
        out[(size_t)(t+0)*25600 + q] = o;
        m = b.x - s0; s0 = (m > 1.f) ? 1.f : 0.f; o.x = (unsigned char)(m > 1.f);
        m = b.y - s1; s1 = (m > 1.f) ? 1.f : 0.f; o.y = (unsigned char)(m > 1.f);
        m = b.z - s2; s2 = (m > 1.f) ? 1.f : 0.f; o.z = (unsigned char)(m > 1.f);
        m = b.w - s3; s3 = (m > 1.f) ? 1.f : 0.f; o.w = (unsigned char)(m > 1.f);
        out[(size_t)(t+1)*25600 + q] = o;
    }
}

// ---------------- k6: FC, 16 (t,b) pairs per block -------------------------
__global__ __launch_bounds__(320) void k_fc(const float* __restrict__ Wh2) {
    __shared__ unsigned char sS[16*1600];
    int tb0 = blockIdx.x * 16;
    int o = threadIdx.x >> 5, lane = threadIdx.x & 31;
    for (int i = threadIdx.x; i < 16*1600/16; i += 320)
        *(uint4*)&sS[i*16] = *(const uint4*)&g_spkh1[(size_t)tb0*1600 + i*16];
    __syncthreads();
    const float* w = Wh2 + o*1600;
    #pragma unroll 1
    for (int p = 0; p < 16; p++) {
        const unsigned char* s = &sS[p*1600];
        float acc = 0.f;
        for (int f = lane; f < 1600; f += 32) acc += (float)s[f] * w[f];
        #pragma unroll
        for (int off = 16; off; off >>= 1) acc += __shfl_down_sync(0xffffffffu, acc, off);
        if (lane == 0) g_fc[(tb0 + p)*10 + o] = acc;
    }
}

// ---------------- k7: output LIF scan + write spikes and mem ---------------
__global__ void k_lif3(float* __restrict__ out) {
    int i = blockIdx.x * blockDim.x + threadIdx.x;
    if (i >= BATCH*10) return;
    float spk = 0.f;
    for (int t = 0; t < STEPS; t++) {
        float mem = g_fc[t*640 + i] - spk;
        spk = (mem > 1.0f) ? 1.0f : 0.0f;
        out[t*640 + i] = spk;                    // out_spikes [100,64,10]
        out[STEPS*640 + t*640 + i] = mem;        // memh2      [100,64,10]
    }
}

// ---------------- launcher -------------------------------------------------
extern "C" void kernel_launch(void* const* d_in, const int* in_sizes, int n_in,
                              void* d_out, int out_size) {
    const float* x   = (const float*)d_in[0];   // [64,3,32,32]
    const float* Win = (const float*)d_in[1];   // [32,3,5,5]
    const float* Wh1 = (const float*)d_in[2];   // [64,32,5,5]
    const float* Wh2 = (const float*)d_in[3];   // [10,1600]
    float* out = (float*)d_out;

    k_fold  <<<288, 256>>>(Win, Wh1);
    k_spikes<<<NSPK/4/256, 256>>>(x);
    k_conv1 <<<TB/2, 224>>>();
    k_lif1  <<<N1/256, 256>>>();
    k_conv2 <<<1600, 256>>>();
    k_lif2  <<<N2/4/256, 256>>>();
    k_fc    <<<TB/16, 320>>>(Wh2);
    k_lif3  <<<3, 256>>>(out);
}

// round 9
// speedup vs baseline: 1.4268x; 1.4268x over previous
#include <cuda_runtime.h>
#include <cstdint>
#include <cstddef>

typedef unsigned long long ull;

// ---------------- problem constants ----------------
#define STEPS 100
#define BATCH 64
#define NSPK  (STEPS*BATCH*3*32*32)   // 19,660,800
#define XSZ   (BATCH*3*32*32)         // 196,608
#define N1    (BATCH*32*14*14)        // 401,408  (layer-1 neurons per step)
#define N2    (BATCH*64*5*5)          // 102,400  (layer-2 neurons per step)
#define TB    (STEPS*BATCH)           // 6400

// ---------------- scratch (device globals; no cudaMalloc allowed) ----------
__device__ __align__(16) unsigned char g_spk0[NSPK];          // poisson spikes [t][b][c][h][w]
__device__ __align__(16) float g_curin[(size_t)STEPS*N1];     // [t][b][sp196][oc32]
__device__ unsigned int  g_spk1[(size_t)STEPS*BATCH*196];     // [t][b*196+sp] -> 32-bit oc mask
__device__ __align__(16) float g_curh1[(size_t)STEPS*N2];     // [t][b][oc64*25+sp]
__device__ __align__(16) unsigned char g_spkh1[(size_t)STEPS*N2];
__device__ float         g_fc[STEPS*BATCH*10];
__device__ __align__(16) float g_Wp1[3*36*32];                // pooled conv1 W [c][uv6x6][oc32]
__device__ __align__(16) float g_Wp2[32*36*64];               // pooled conv2 W [c][uv6x6][oc64]

// ---------------- packed f32x2 helpers (bit-exact fp32 pairs) --------------
__device__ __forceinline__ void ffma2(ull& d, ull a, ull b) {
    asm("fma.rn.f32x2 %0, %1, %2, %0;" : "+l"(d) : "l"(a), "l"(b));
}
__device__ __forceinline__ void fadd2(ull& d, ull a) {
    asm("add.rn.f32x2 %0, %0, %1;" : "+l"(d) : "l"(a));
}
__device__ __forceinline__ ull pack_dup(float f) {
    ull p; asm("mov.b64 %0, {%1, %1};" : "=l"(p) : "f"(f)); return p;
}
__device__ __forceinline__ void unpack2(ull p, float& lo, float& hi) {
    asm("mov.b64 {%0, %1}, %2;" : "=f"(lo), "=f"(hi) : "l"(p));
}

// ---------------- threefry2x32 (JAX-exact, partitionable path) -------------
__device__ __forceinline__ uint2 threefry2x32(uint32_t k0, uint32_t k1,
                                              uint32_t x0, uint32_t x1) {
    uint32_t ks0 = k0, ks1 = k1, ks2 = k0 ^ k1 ^ 0x1BD11BDAu;
    x0 += ks0; x1 += ks1;
#define TFR(r) { x0 += x1; x1 = (x1 << (r)) | (x1 >> (32 - (r))); x1 ^= x0; }
    TFR(13) TFR(15) TFR(26) TFR(6)
    x0 += ks1; x1 += ks2 + 1u;
    TFR(17) TFR(29) TFR(16) TFR(24)
    x0 += ks2; x1 += ks0 + 2u;
    TFR(13) TFR(15) TFR(26) TFR(6)
    x0 += ks0; x1 += ks1 + 3u;
    TFR(17) TFR(29) TFR(16) TFR(24)
    x0 += ks1; x1 += ks2 + 4u;
    TFR(13) TFR(15) TFR(26) TFR(6)
    x0 += ks2; x1 += ks0 + 5u;
#undef TFR
    return make_uint2(x0, x1);
}

// ---------------- k0: fold avgpool(2x2,*0.25) into conv weights ------------
__global__ void k_fold(const float* __restrict__ Win, const float* __restrict__ Wh1) {
    int i = blockIdx.x * blockDim.x + threadIdx.x;
    if (i < 3*36*32) {
        int oc = i & 31; int r = i >> 5; int uv = r % 36; int c = r / 36;
        int u = uv / 6, v = uv % 6;
        float s = 0.f;
        #pragma unroll
        for (int dh = 0; dh < 2; dh++)
            #pragma unroll
            for (int dw = 0; dw < 2; dw++) {
                int kh = u - dh, kw = v - dw;
                if (kh >= 0 && kh < 5 && kw >= 0 && kw < 5)
                    s += Win[(oc*3 + c)*25 + kh*5 + kw];
            }
        g_Wp1[i] = 0.25f * s;
    }
    if (i < 32*36*64) {
        int oc = i & 63; int r = i >> 6; int uv = r % 36; int c = r / 36;
        int u = uv / 6, v = uv % 6;
        float s = 0.f;
        #pragma unroll
        for (int dh = 0; dh < 2; dh++)
            #pragma unroll
            for (int dw = 0; dw < 2; dw++) {
                int kh = u - dh, kw = v - dw;
                if (kh >= 0 && kh < 5 && kw >= 0 && kw < 5)
                    s += Wh1[(oc*32 + c)*25 + kh*5 + kw];
            }
        g_Wp2[i] = 0.25f * s;
    }
}

// ---------------- k1: poisson spikes, ILP-4 --------------------------------
__global__ void k_spikes(const float* __restrict__ x) {
    int q = blockIdx.x * 256 + threadIdx.x;      // quad index < NSPK/4
    int i0 = q << 2;
    const float4 xv = *(const float4*)&x[i0 % XSZ];   // XSZ % 4 == 0: no wrap
    uint2 r0 = threefry2x32(0u, 1u, 0u, (uint32_t)(i0 + 0));
    uint2 r1 = threefry2x32(0u, 1u, 0u, (uint32_t)(i0 + 1));
    uint2 r2 = threefry2x32(0u, 1u, 0u, (uint32_t)(i0 + 2));
    uint2 r3 = threefry2x32(0u, 1u, 0u, (uint32_t)(i0 + 3));
    uchar4 o;
    float u;
    u = __uint_as_float(((r0.x ^ r0.y) >> 9) | 0x3f800000u) - 1.0f; o.x = (u < xv.x * 2.0f);
    u = __uint_as_float(((r1.x ^ r1.y) >> 9) | 0x3f800000u) - 1.0f; o.y = (u < xv.y * 2.0f);
    u = __uint_as_float(((r2.x ^ r2.y) >> 9) | 0x3f800000u) - 1.0f; o.z = (u < xv.z * 2.0f);
    u = __uint_as_float(((r3.x ^ r3.y) >> 9) | 0x3f800000u) - 1.0f; o.w = (u < xv.w * 2.0f);
    ((uchar4*)g_spk0)[q] = o;
}

// ---------------- k2: conv1+pool, f32x2, 196 workers = (oc-half, sp-pair) --
__global__ __launch_bounds__(224) void k_conv1(void) {
    __shared__ float sIn[3*32*32];
    __shared__ __align__(16) float sW[3*36*32];
    int tb = blockIdx.x;
    int tid = threadIdx.x;
    const uchar4* inp = (const uchar4*)(g_spk0 + (size_t)tb * 3072);
    for (int i = tid; i < 768; i += 224) {
        uchar4 b4 = inp[i];
        float4 f4 = make_float4((float)b4.x, (float)b4.y, (float)b4.z, (float)b4.w);
        *(float4*)&sIn[i*4] = f4;
    }
    for (int i = tid; i < 3456; i += 224) sW[i] = g_Wp1[i];
    __syncthreads();
    if (tid >= 196) return;

    int oh  = tid / 98;               // oc half: oc = oh*16 .. +15
    int spi = tid - oh*98;            // sp pair: sp0 = 2*spi, sp1 = 2*spi+1
    int sp0 = 2*spi;
    int ph = sp0 / 14, pw = sp0 % 14;
    int ia = ph*64 + pw*2;            // (2ph)*32 + 2pw ; sp1 input base = ia+2
    ull accA[8], accB[8];
    #pragma unroll
    for (int j = 0; j < 8; j++) { accA[j] = 0ull; accB[j] = 0ull; }

    #pragma unroll 1
    for (int c = 0; c < 3; c++) {
        const float* sIc = &sIn[c*1024 + ia];
        const float* wc  = &sW[c*1152 + oh*16];
        #pragma unroll 1
        for (int u = 0; u < 6; u++) {
            #pragma unroll
            for (int v = 0; v < 6; v++) {
                ull sa = pack_dup(sIc[u*32 + v]);
                ull sb = pack_dup(sIc[u*32 + v + 2]);
                const ull* w = (const ull*)&wc[(u*6 + v)*32];
                #pragma unroll
                for (int j = 0; j < 8; j++) {
                    ull wj = w[j];
                    ffma2(accA[j], wj, sa);
                    ffma2(accB[j], wj, sb);
                }
            }
        }
    }
    ull* oA = (ull*)&g_curin[(size_t)tb*6272 + sp0*32 + oh*16];
    ull* oB = (ull*)&g_curin[(size_t)tb*6272 + (sp0+1)*32 + oh*16];
    #pragma unroll
    for (int j = 0; j < 8; j++) { oA[j] = accA[j]; oB[j] = accB[j]; }
}

// ---------------- k3: LIF scan layer 1 -> ballot bitmasks ------------------
__global__ void k_lif1(void) {
    int n = blockIdx.x*256 + threadIdx.x;       // < 401408 ; n = (b*196+sp)*32+oc
    int lane = threadIdx.x & 31;
    int bs = n >> 5;                            // b*196 + sp
    const float* cur = g_curin + n;
    unsigned* out = g_spk1 + bs;
    float spk = 0.f;
    #pragma unroll 1
    for (int t = 0; t < STEPS; t += 4) {
        float c0 = cur[(size_t)(t+0)*N1];
        float c1 = cur[(size_t)(t+1)*N1];
        float c2 = cur[(size_t)(t+2)*N1];
        float c3 = cur[(size_t)(t+3)*N1];
        float mem; unsigned m0, m1, m2, m3;
        mem = c0 - spk; spk = (mem > 1.f) ? 1.f : 0.f; m0 = __ballot_sync(0xffffffffu, mem > 1.f);
        mem = c1 - spk; spk = (mem > 1.f) ? 1.f : 0.f; m1 = __ballot_sync(0xffffffffu, mem > 1.f);
        mem = c2 - spk; spk = (mem > 1.f) ? 1.f : 0.f; m2 = __ballot_sync(0xffffffffu, mem > 1.f);
        mem = c3 - spk; spk = (mem > 1.f) ? 1.f : 0.f; m3 = __ballot_sync(0xffffffffu, mem > 1.f);
        if (lane == 0) {
            out[(size_t)(t+0)*12544] = m0;
            out[(size_t)(t+1)*12544] = m1;
            out[(size_t)(t+2)*12544] = m2;
            out[(size_t)(t+3)*12544] = m3;
        }
    }
}

// ---------------- k4: conv2+pool, mask-windowed sparse, t-group of 2 -------
// (R5 structure; t-group halved 4->2 to cut acc regs 32->16 for occupancy)
__global__ __launch_bounds__(256) void k_conv2(void) {
    __shared__ __align__(16) float sW[36*64];   // per-channel weights
    __shared__ unsigned sMask2[2*196];          // oc-masks for 2 t
    __shared__ unsigned sRow[2][32*14];         // per-t per-channel row masks

    int tid = threadIdx.x;
    int b   = blockIdx.x & 63;
    int tg  = blockIdx.x >> 6;                  // 0..49
    int t0  = tg * 2;

    for (int i = tid; i < 2*196; i += 256) {
        int tt = i / 196, sp = i - tt*196;
        sMask2[i] = g_spk1[(size_t)(t0 + tt)*12544 + b*196 + sp];
    }
    __syncthreads();
    if (tid < 224) {                            // transpose to row bitmasks
        int c = tid & 31; int rp = tid >> 5;    // rp 0..6
        #pragma unroll
        for (int tt = 0; tt < 2; tt++) {
            const unsigned* mk = &sMask2[tt*196];
            #pragma unroll
            for (int rr = 0; rr < 2; rr++) {
                int ih = rp*2 + rr;
                unsigned m = 0;
                #pragma unroll
                for (int iw = 0; iw < 14; iw++)
                    m |= ((mk[ih*14 + iw] >> c) & 1u) << iw;
                sRow[tt][c*14 + ih] = m;
            }
        }
    }

    int active = (tid < 200);
    int sp = tid >> 3, og = tid & 7;            // sp 0..24, oc octet og*8..+7
    int ph = sp / 5, pw = sp % 5;
    int shift = 2*pw;
    ull acc[2][4];
    #pragma unroll
    for (int tt = 0; tt < 2; tt++)
        #pragma unroll
        for (int j = 0; j < 4; j++) acc[tt][j] = 0ull;

    #pragma unroll 1
    for (int c = 0; c < 32; c++) {
        __syncthreads();                        // prev gather done (and transpose, 1st iter)
        for (int i = tid; i < 576; i += 256)
            *(float4*)&sW[i*4] = *(const float4*)&g_Wp2[c*2304 + i*4];
        __syncthreads();
        if (active) {
            #pragma unroll
            for (int tt = 0; tt < 2; tt++) {
                const unsigned* rc = &sRow[tt][c*14 + 2*ph];
                #pragma unroll
                for (int u = 0; u < 6; u++) {
                    unsigned bits = (rc[u] >> shift) & 63u;
                    while (bits) {
                        int v = __ffs(bits) - 1; bits &= bits - 1;
                        const ull* w = (const ull*)&sW[(u*6 + v)*64 + og*8];
                        fadd2(acc[tt][0], w[0]); fadd2(acc[tt][1], w[1]);
                        fadd2(acc[tt][2], w[2]); fadd2(acc[tt][3], w[3]);
                    }
                }
            }
        }
    }

    if (active) {
        #pragma unroll
        for (int tt = 0; tt < 2; tt++) {
            size_t ob = (size_t)((t0 + tt)*64 + b)*1600 + (size_t)(og*8)*25 + sp;
            float f[8];
            unpack2(acc[tt][0], f[0], f[1]); unpack2(acc[tt][1], f[2], f[3]);
            unpack2(acc[tt][2], f[4], f[5]); unpack2(acc[tt][3], f[6], f[7]);
            #pragma unroll
            for (int j = 0; j < 8; j++) g_curh1[ob + j*25] = f[j];
        }
    }
}

// ---------------- k5: LIF scan layer 2 (float4, unroll2) -------------------
__global__ void k_lif2(void) {
    int q = blockIdx.x*256 + threadIdx.x;       // < 25600 float4-neurons
    const float4* cur = (const float4*)g_curh1;
    uchar4* out = (uchar4*)g_spkh1;
    float s0 = 0.f, s1 = 0.f, s2 = 0.f, s3 = 0.f;
    #pragma unroll 1
    for (int t = 0; t < STEPS; t += 2) {
        float4 a = cur[(size_t)(t+0)*25600 + q];
        float4 b = cur[(size_t)(t+1)*25600 + q];
        float m; uchar4 o;
        m = a.x - s0; s0 = (m > 1.f) ? 1.f : 0.f; o.x = (unsigned char)(m > 1.f);
        m = a.y - s1; s1 = (m > 1.f) ? 1.f : 0.f; o.y = (unsigned char)(m > 1.f);
        m = a.z - s2; s2 = (m > 1.f) ? 1.f : 0.f; o.z = (unsigned char)(m > 1.f);
        m = a.w - s3; s3 = (m > 1.f) ? 1.f : 0.f; o.w = (unsigned char)(m > 1.f);
        out[(size_t)(t+0)*25600 + q] = o;
        m = b.x - s0; s0 = (m > 1.f) ? 1.f : 0.f; o.x = (unsigned char)(m > 1.f);
        m = b.y - s1; s1 = (m > 1.f) ? 1.f : 0.f; o.y = (unsigned char)(m > 1.f);
        m = b.z - s2; s2 = (m > 1.f) ? 1.f : 0.f; o.z = (unsigned char)(m > 1.f);
        m = b.w - s3; s3 = (m > 1.f) ? 1.f : 0.f; o.w = (unsigned char)(m > 1.f);
        out[(size_t)(t+1)*25600 + q] = o;
    }
}

// ---------------- k6: FC, 16 (t,b) pairs per block -------------------------
__global__ __launch_bounds__(320) void k_fc(const float* __restrict__ Wh2) {
    __shared__ unsigned char sS[16*1600];
    int tb0 = blockIdx.x * 16;
    int o = threadIdx.x >> 5, lane = threadIdx.x & 31;
    for (int i = threadIdx.x; i < 16*1600/16; i += 320)
        *(uint4*)&sS[i*16] = *(const uint4*)&g_spkh1[(size_t)tb0*1600 + i*16];
    __syncthreads();
    const float* w = Wh2 + o*1600;
    #pragma unroll 1
    for (int p = 0; p < 16; p++) {
        const unsigned char* s = &sS[p*1600];
        float acc = 0.f;
        for (int f = lane; f < 1600; f += 32) acc += (float)s[f] * w[f];
        #pragma unroll
        for (int off = 16; off; off >>= 1) acc += __shfl_down_sync(0xffffffffu, acc, off);
        if (lane == 0) g_fc[(tb0 + p)*10 + o] = acc;
    }
}

// ---------------- k7: output LIF scan + write spikes and mem ---------------
__global__ void k_lif3(float* __restrict__ out) {
    int i = blockIdx.x * blockDim.x + threadIdx.x;
    if (i >= BATCH*10) return;
    float spk = 0.f;
    for (int t = 0; t < STEPS; t++) {
        float mem = g_fc[t*640 + i] - spk;
        spk = (mem > 1.0f) ? 1.0f : 0.0f;
        out[t*640 + i] = spk;                    // out_spikes [100,64,10]
        out[STEPS*640 + t*640 + i] = mem;        // memh2      [100,64,10]
    }
}

// ---------------- launcher -------------------------------------------------
extern "C" void kernel_launch(void* const* d_in, const int* in_sizes, int n_in,
                              void* d_out, int out_size) {
    const float* x   = (const float*)d_in[0];   // [64,3,32,32]
    const float* Win = (const float*)d_in[1];   // [32,3,5,5]
    const float* Wh1 = (const float*)d_in[2];   // [64,32,5,5]
    const float* Wh2 = (const float*)d_in[3];   // [10,1600]
    float* out = (float*)d_out;

    k_fold  <<<288, 256>>>(Win, Wh1);
    k_spikes<<<NSPK/4/256, 256>>>(x);
    k_conv1 <<<TB, 224>>>();
    k_lif1  <<<N1/256, 256>>>();
    k_conv2 <<<3200, 256>>>();
    k_lif2  <<<N2/4/256, 256>>>();
    k_fc    <<<TB/16, 320>>>(Wh2);
    k_lif3  <<<3, 256>>>(out);
}

// round 10
// speedup vs baseline: 1.4624x; 1.0249x over previous
#include <cuda_runtime.h>
#include <cstdint>
#include <cstddef>

typedef unsigned long long ull;

// ---------------- problem constants ----------------
#define STEPS 100
#define BATCH 64
#define NSPK  (STEPS*BATCH*3*32*32)   // 19,660,800
#define XSZ   (BATCH*3*32*32)         // 196,608
#define N1    (BATCH*32*14*14)        // 401,408  (layer-1 neurons per step)
#define N2    (BATCH*64*5*5)          // 102,400  (layer-2 neurons per step)
#define TB    (STEPS*BATCH)           // 6400

// ---------------- scratch (device globals; no cudaMalloc allowed) ----------
__device__ __align__(16) unsigned char g_spk0[NSPK];          // poisson spikes [t][b][c][h][w]
__device__ __align__(16) float g_curin[(size_t)STEPS*N1];     // [t][b][sp196][oc32]
__device__ unsigned int  g_spk1[(size_t)STEPS*BATCH*196];     // [t][b*196+sp] -> 32-bit oc mask
__device__ __align__(16) float g_curh1[(size_t)STEPS*N2];     // [t][b][oc64*25+sp]
__device__ __align__(16) unsigned char g_spkh1[(size_t)STEPS*N2];
__device__ float         g_fc[STEPS*BATCH*10];
__device__ __align__(16) float g_Wp1[3*36*32];                // pooled conv1 W [c][uv6x6][oc32]
__device__ __align__(16) float g_Wp2[32*36*64];               // pooled conv2 W [c][uv6x6][oc64]

// ---------------- packed f32x2 helpers (bit-exact fp32 pairs) --------------
__device__ __forceinline__ void ffma2(ull& d, ull a, ull b) {
    asm("fma.rn.f32x2 %0, %1, %2, %0;" : "+l"(d) : "l"(a), "l"(b));
}
__device__ __forceinline__ void fadd2(ull& d, ull a) {
    asm("add.rn.f32x2 %0, %0, %1;" : "+l"(d) : "l"(a));
}
__device__ __forceinline__ ull pack_dup(float f) {
    ull p; asm("mov.b64 %0, {%1, %1};" : "=l"(p) : "f"(f)); return p;
}
__device__ __forceinline__ void unpack2(ull p, float& lo, float& hi) {
    asm("mov.b64 {%0, %1}, %2;" : "=f"(lo), "=f"(hi) : "l"(p));
}

// ---------------- threefry2x32 (JAX-exact, partitionable path) -------------
__device__ __forceinline__ uint2 threefry2x32(uint32_t k0, uint32_t k1,
                                              uint32_t x0, uint32_t x1) {
    uint32_t ks0 = k0, ks1 = k1, ks2 = k0 ^ k1 ^ 0x1BD11BDAu;
    x0 += ks0; x1 += ks1;
#define TFR(r) { x0 += x1; x1 = (x1 << (r)) | (x1 >> (32 - (r))); x1 ^= x0; }
    TFR(13) TFR(15) TFR(26) TFR(6)
    x0 += ks1; x1 += ks2 + 1u;
    TFR(17) TFR(29) TFR(16) TFR(24)
    x0 += ks2; x1 += ks0 + 2u;
    TFR(13) TFR(15) TFR(26) TFR(6)
    x0 += ks0; x1 += ks1 + 3u;
    TFR(17) TFR(29) TFR(16) TFR(24)
    x0 += ks1; x1 += ks2 + 4u;
    TFR(13) TFR(15) TFR(26) TFR(6)
    x0 += ks2; x1 += ks0 + 5u;
#undef TFR
    return make_uint2(x0, x1);
}

// ---------------- k0: fold avgpool(2x2,*0.25) into conv weights ------------
__global__ void k_fold(const float* __restrict__ Win, const float* __restrict__ Wh1) {
    int i = blockIdx.x * blockDim.x + threadIdx.x;
    if (i < 3*36*32) {
        int oc = i & 31; int r = i >> 5; int uv = r % 36; int c = r / 36;
        int u = uv / 6, v = uv % 6;
        float s = 0.f;
        #pragma unroll
        for (int dh = 0; dh < 2; dh++)
            #pragma unroll
            for (int dw = 0; dw < 2; dw++) {
                int kh = u - dh, kw = v - dw;
                if (kh >= 0 && kh < 5 && kw >= 0 && kw < 5)
                    s += Win[(oc*3 + c)*25 + kh*5 + kw];
            }
        g_Wp1[i] = 0.25f * s;
    }
    if (i < 32*36*64) {
        int oc = i & 63; int r = i >> 6; int uv = r % 36; int c = r / 36;
        int u = uv / 6, v = uv % 6;
        float s = 0.f;
        #pragma unroll
        for (int dh = 0; dh < 2; dh++)
            #pragma unroll
            for (int dw = 0; dw < 2; dw++) {
                int kh = u - dh, kw = v - dw;
                if (kh >= 0 && kh < 5 && kw >= 0 && kw < 5)
                    s += Wh1[(oc*32 + c)*25 + kh*5 + kw];
            }
        g_Wp2[i] = 0.25f * s;
    }
}

// ---------------- k1: poisson spikes, ILP-4 --------------------------------
__global__ void k_spikes(const float* __restrict__ x) {
    int q = blockIdx.x * 256 + threadIdx.x;      // quad index < NSPK/4
    int i0 = q << 2;
    const float4 xv = *(const float4*)&x[i0 % XSZ];   // XSZ % 4 == 0: no wrap
    uint2 r0 = threefry2x32(0u, 1u, 0u, (uint32_t)(i0 + 0));
    uint2 r1 = threefry2x32(0u, 1u, 0u, (uint32_t)(i0 + 1));
    uint2 r2 = threefry2x32(0u, 1u, 0u, (uint32_t)(i0 + 2));
    uint2 r3 = threefry2x32(0u, 1u, 0u, (uint32_t)(i0 + 3));
    uchar4 o;
    float u;
    u = __uint_as_float(((r0.x ^ r0.y) >> 9) | 0x3f800000u) - 1.0f; o.x = (u < xv.x * 2.0f);
    u = __uint_as_float(((r1.x ^ r1.y) >> 9) | 0x3f800000u) - 1.0f; o.y = (u < xv.y * 2.0f);
    u = __uint_as_float(((r2.x ^ r2.y) >> 9) | 0x3f800000u) - 1.0f; o.z = (u < xv.z * 2.0f);
    u = __uint_as_float(((r3.x ^ r3.y) >> 9) | 0x3f800000u) - 1.0f; o.w = (u < xv.w * 2.0f);
    ((uchar4*)g_spk0)[q] = o;
}

// ---------------- conv1 compute core ---------------------------------------
__device__ __forceinline__ void conv1_compute(const float* __restrict__ sIn,
                                              const float* __restrict__ sW,
                                              int tb, int oh, int sp0, int ia) {
    ull accA[8], accB[8];
    #pragma unroll
    for (int j = 0; j < 8; j++) { accA[j] = 0ull; accB[j] = 0ull; }

    #pragma unroll 1
    for (int c = 0; c < 3; c++) {
        const float* sIc = &sIn[c*1024 + ia];
        const float* wc  = &sW[c*1152 + oh*16];
        #pragma unroll 1
        for (int u = 0; u < 6; u++) {
            #pragma unroll
            for (int v = 0; v < 6; v++) {
                ull sa = pack_dup(sIc[u*32 + v]);
                ull sb = pack_dup(sIc[u*32 + v + 2]);
                const ull* w = (const ull*)&wc[(u*6 + v)*32];
                #pragma unroll
                for (int j = 0; j < 8; j++) {
                    ull wj = w[j];
                    ffma2(accA[j], wj, sa);
                    ffma2(accB[j], wj, sb);
                }
            }
        }
    }
    ull* oA = (ull*)&g_curin[(size_t)tb*6272 + sp0*32 + oh*16];
    ull* oB = (ull*)&g_curin[(size_t)tb*6272 + (sp0+1)*32 + oh*16];
    #pragma unroll
    for (int j = 0; j < 8; j++) { oA[j] = accA[j]; oB[j] = accB[j]; }
}

// ---------------- k2: conv1+pool, 2 (t,b) tiles per block, smem-staged -----
// both input tiles + weights staged before ONE sync; weights amortized x2
__global__ __launch_bounds__(224) void k_conv1(void) {
    __shared__ float sIn[2][3*32*32];                 // 24KB
    __shared__ __align__(16) float sW[3*36*32];       // 13.5KB
    int tid = threadIdx.x;
    int tb0 = blockIdx.x * 2;

    #pragma unroll
    for (int tile = 0; tile < 2; tile++) {
        const uchar4* inp = (const uchar4*)(g_spk0 + (size_t)(tb0 + tile) * 3072);
        for (int i = tid; i < 768; i += 224) {
            uchar4 b4 = inp[i];
            *(float4*)&sIn[tile][i*4] =
                make_float4((float)b4.x, (float)b4.y, (float)b4.z, (float)b4.w);
        }
    }
    for (int i = tid; i < 3456; i += 224) sW[i] = g_Wp1[i];
    __syncthreads();
    if (tid >= 196) return;

    int oh  = tid / 98;               // oc half: oc = oh*16 .. +15
    int spi = tid - oh*98;            // sp pair
    int sp0 = 2*spi;
    int ph = sp0 / 14, pw = sp0 % 14;
    int ia = ph*64 + pw*2;            // (2ph)*32 + 2pw

    conv1_compute(sIn[0], sW, tb0, oh, sp0, ia);
    conv1_compute(sIn[1], sW, tb0 + 1, oh, sp0, ia);
}

// ---------------- k3: LIF scan layer 1 -> ballot bitmasks ------------------
__global__ void k_lif1(void) {
    int n = blockIdx.x*256 + threadIdx.x;       // < 401408 ; n = (b*196+sp)*32+oc
    int lane = threadIdx.x & 31;
    int bs = n >> 5;                            // b*196 + sp
    const float* cur = g_curin + n;
    unsigned* out = g_spk1 + bs;
    float spk = 0.f;
    #pragma unroll 1
    for (int t = 0; t < STEPS; t += 4) {
        float c0 = cur[(size_t)(t+0)*N1];
        float c1 = cur[(size_t)(t+1)*N1];
        float c2 = cur[(size_t)(t+2)*N1];
        float c3 = cur[(size_t)(t+3)*N1];
        float mem; unsigned m0, m1, m2, m3;
        mem = c0 - spk; spk = (mem > 1.f) ? 1.f : 0.f; m0 = __ballot_sync(0xffffffffu, mem > 1.f);
        mem = c1 - spk; spk = (mem > 1.f) ? 1.f : 0.f; m1 = __ballot_sync(0xffffffffu, mem > 1.f);
        mem = c2 - spk; spk = (mem > 1.f) ? 1.f : 0.f; m2 = __ballot_sync(0xffffffffu, mem > 1.f);
        mem = c3 - spk; spk = (mem > 1.f) ? 1.f : 0.f; m3 = __ballot_sync(0xffffffffu, mem > 1.f);
        if (lane == 0) {
            out[(size_t)(t+0)*12544] = m0;
            out[(size_t)(t+1)*12544] = m1;
            out[(size_t)(t+2)*12544] = m2;
            out[(size_t)(t+3)*12544] = m3;
        }
    }
}

// ---------------- k4: conv2+pool, mask-windowed sparse, t-group of 4,
//                  TWO channels staged per sync ----------------------------
__global__ __launch_bounds__(256) void k_conv2(void) {
    __shared__ __align__(16) float sW[2*36*64]; // channels cc, cc+1 (18.4KB)
    __shared__ unsigned sMask4[4*196];          // oc-masks for 4 t
    __shared__ unsigned sRow[4][32*14];         // per-t per-channel row masks

    int tid = threadIdx.x;
    int b   = blockIdx.x & 63;
    int tg  = blockIdx.x >> 6;                  // 0..24
    int t0  = tg * 4;

    for (int i = tid; i < 4*196; i += 256) {
        int tt = i / 196, sp = i - tt*196;
        sMask4[i] = g_spk1[(size_t)(t0 + tt)*12544 + b*196 + sp];
    }
    __syncthreads();
    if (tid < 224) {                            // transpose to row bitmasks
        int c = tid & 31; int rp = tid >> 5;    // rp 0..6
        #pragma unroll
        for (int tt = 0; tt < 4; tt++) {
            const unsigned* mk = &sMask4[tt*196];
            #pragma unroll
            for (int rr = 0; rr < 2; rr++) {
                int ih = rp*2 + rr;
                unsigned m = 0;
                #pragma unroll
                for (int iw = 0; iw < 14; iw++)
                    m |= ((mk[ih*14 + iw] >> c) & 1u) << iw;
                sRow[tt][c*14 + ih] = m;
            }
        }
    }

    int active = (tid < 200);
    int sp = tid >> 3, og = tid & 7;            // sp 0..24, oc octet og*8..+7
    int ph = sp / 5, pw = sp % 5;
    int shift = 2*pw;
    ull acc[4][4];
    #pragma unroll
    for (int tt = 0; tt < 4; tt++)
        #pragma unroll
        for (int j = 0; j < 4; j++) acc[tt][j] = 0ull;

    #pragma unroll 1
    for (int cc = 0; cc < 32; cc += 2) {
        __syncthreads();                        // prev gather done (and transpose, 1st iter)
        for (int i = tid; i < 1152; i += 256)   // stage channels cc and cc+1
            *(float4*)&sW[i*4] = *(const float4*)&g_Wp2[cc*2304 + i*4];
        __syncthreads();
        #pragma unroll
        for (int half = 0; half < 2; half++) {  // c = cc, cc+1 (ascending: bit-exact)
            int c = cc + half;
            const float* wbuf = &sW[half*2304];
            if (active) {
                #pragma unroll
                for (int tt = 0; tt < 4; tt++) {
                    const unsigned* rc = &sRow[tt][c*14 + 2*ph];
                    #pragma unroll
                    for (int u = 0; u < 6; u++) {
                        unsigned bits = (rc[u] >> shift) & 63u;
                        while (bits) {
                            int v = __ffs(bits) - 1; bits &= bits - 1;
                            const ull* w = (const ull*)&wbuf[(u*6 + v)*64 + og*8];
                            fadd2(acc[tt][0], w[0]); fadd2(acc[tt][1], w[1]);
                            fadd2(acc[tt][2], w[2]); fadd2(acc[tt][3], w[3]);
                        }
                    }
                }
            }
        }
    }

    if (active) {
        #pragma unroll
        for (int tt = 0; tt < 4; tt++) {
            size_t ob = (size_t)((t0 + tt)*64 + b)*1600 + (size_t)(og*8)*25 + sp;
            float f[8];
            unpack2(acc[tt][0], f[0], f[1]); unpack2(acc[tt][1], f[2], f[3]);
            unpack2(acc[tt][2], f[4], f[5]); unpack2(acc[tt][3], f[6], f[7]);
            #pragma unroll
            for (int j = 0; j < 8; j++) g_curh1[ob + j*25] = f[j];
        }
    }
}

// ---------------- k5: LIF scan layer 2 (float4, unroll2) -------------------
__global__ void k_lif2(void) {
    int q = blockIdx.x*256 + threadIdx.x;       // < 25600 float4-neurons
    const float4* cur = (const float4*)g_curh1;
    uchar4* out = (uchar4*)g_spkh1;
    float s0 = 0.f, s1 = 0.f, s2 = 0.f, s3 = 0.f;
    #pragma unroll 1
    for (int t = 0; t < STEPS; t += 2) {
        float4 a = cur[(size_t)(t+0)*25600 + q];
        float4 b = cur[(size_t)(t+1)*25600 + q];
        float m; uchar4 o;
        m = a.x - s0; s0 = (m > 1.f) ? 1.f : 0.f; o.x = (unsigned char)(m > 1.f);
        m = a.y - s1; s1 = (m > 1.f) ? 1.f : 0.f; o.y = (unsigned char)(m > 1.f);
        m = a.z - s2; s2 = (m > 1.f) ? 1.f : 0.f; o.z = (unsigned char)(m > 1.f);
        m = a.w - s3; s3 = (m > 1.f) ? 1.f : 0.f; o.w = (unsigned char)(m > 1.f);
        out[(size_t)(t+0)*25600 + q] = o;
        m = b.x - s0; s0 = (m > 1.f) ? 1.f : 0.f; o.x = (unsigned char)(m > 1.f);
        m = b.y - s1; s1 = (m > 1.f) ? 1.f : 0.f; o.y = (unsigned char)(m > 1.f);
        m = b.z - s2; s2 = (m > 1.f) ? 1.f : 0.f; o.z = (unsigned char)(m > 1.f);
        m = b.w - s3; s3 = (m > 1.f) ? 1.f : 0.f; o.w = (unsigned char)(m > 1.f);
        out[(size_t)(t+1)*25600 + q] = o;
    }
}

// ---------------- k6: FC, 16 (t,b) pairs per block -------------------------
__global__ __launch_bounds__(320) void k_fc(const float* __restrict__ Wh2) {
    __shared__ unsigned char sS[16*1600];
    int tb0 = blockIdx.x * 16;
    int o = threadIdx.x >> 5, lane = threadIdx.x & 31;
    for (int i = threadIdx.x; i < 16*1600/16; i += 320)
        *(uint4*)&sS[i*16] = *(const uint4*)&g_spkh1[(size_t)tb0*1600 + i*16];
    __syncthreads();
    const float* w = Wh2 + o*1600;
    #pragma unroll 1
    for (int p = 0; p < 16; p++) {
        const unsigned char* s = &sS[p*1600];
        float acc = 0.f;
        for (int f = lane; f < 1600; f += 32) acc += (float)s[f] * w[f];
        #pragma unroll
        for (int off = 16; off; off >>= 1) acc += __shfl_down_sync(0xffffffffu, acc, off);
        if (lane == 0) g_fc[(tb0 + p)*10 + o] = acc;
    }
}

// ---------------- k7: output LIF scan + write spikes and mem ---------------
__global__ void k_lif3(float* __restrict__ out) {
    int i = blockIdx.x * blockDim.x + threadIdx.x;
    if (i >= BATCH*10) return;
    float spk = 0.f;
    for (int t = 0; t < STEPS; t++) {
        float mem = g_fc[t*640 + i] - spk;
        spk = (mem > 1.0f) ? 1.0f : 0.0f;
        out[t*640 + i] = spk;                    // out_spikes [100,64,10]
        out[STEPS*640 + t*640 + i] = mem;        // memh2      [100,64,10]
    }
}

// ---------------- launcher -------------------------------------------------
extern "C" void kernel_launch(void* const* d_in, const int* in_sizes, int n_in,
                              void* d_out, int out_size) {
    const float* x   = (const float*)d_in[0];   // [64,3,32,32]
    const float* Win = (const float*)d_in[1];   // [32,3,5,5]
    const float* Wh1 = (const float*)d_in[2];   // [64,32,5,5]
    const float* Wh2 = (const float*)d_in[3];   // [10,1600]
    float* out = (float*)d_out;

    k_fold  <<<288, 256>>>(Win, Wh1);
    k_spikes<<<NSPK/4/256, 256>>>(x);
    k_conv1 <<<TB/2, 224>>>();
    k_lif1  <<<N1/256, 256>>>();
    k_conv2 <<<1600, 256>>>();
    k_lif2  <<<N2/4/256, 256>>>();
    k_fc    <<<TB/16, 320>>>(Wh2);
    k_lif3  <<<3, 256>>>(out);
}

// round 11
// speedup vs baseline: 1.4674x; 1.0035x over previous
#include <cuda_runtime.h>
#include <cstdint>
#include <cstddef>

typedef unsigned long long ull;

// ---------------- problem constants ----------------
#define STEPS 100
#define BATCH 64
#define NSPK  (STEPS*BATCH*3*32*32)   // 19,660,800
#define XSZ   (BATCH*3*32*32)         // 196,608
#define N1    (BATCH*32*14*14)        // 401,408  (layer-1 neurons per step)
#define N2    (BATCH*64*5*5)          // 102,400  (layer-2 neurons per step)
#define TB    (STEPS*BATCH)           // 6400

// ---------------- scratch (device globals; no cudaMalloc allowed) ----------
__device__ __align__(16) unsigned char g_spk0[NSPK];          // poisson spikes [t][b][c][h][w]
__device__ __align__(16) float g_curin[(size_t)STEPS*N1];     // [t][b][sp196][oc32]
__device__ unsigned int  g_spk1[(size_t)STEPS*BATCH*196];     // [t][b*196+sp] -> 32-bit oc mask
__device__ __align__(16) float g_curh1[(size_t)STEPS*N2];     // [t][b][oc64*25+sp]
__device__ __align__(16) unsigned char g_spkh1[(size_t)STEPS*N2];
__device__ float         g_fc[STEPS*BATCH*10];
__device__ __align__(16) float g_Wp1[3*36*32];                // pooled conv1 W [c][uv6x6][oc32]
__device__ __align__(16) float g_Wp2[32*36*64];               // pooled conv2 W [c][uv6x6][oc64]

// ---------------- packed f32x2 helpers (bit-exact fp32 pairs) --------------
__device__ __forceinline__ void ffma2(ull& d, ull a, ull b) {
    asm("fma.rn.f32x2 %0, %1, %2, %0;" : "+l"(d) : "l"(a), "l"(b));
}
__device__ __forceinline__ void fadd2(ull& d, ull a) {
    asm("add.rn.f32x2 %0, %0, %1;" : "+l"(d) : "l"(a));
}
__device__ __forceinline__ ull pack_dup(float f) {
    ull p; asm("mov.b64 %0, {%1, %1};" : "=l"(p) : "f"(f)); return p;
}
__device__ __forceinline__ void unpack2(ull p, float& lo, float& hi) {
    asm("mov.b64 {%0, %1}, %2;" : "=f"(lo), "=f"(hi) : "l"(p));
}

// ---------------- threefry2x32 (JAX-exact, partitionable path) -------------
__device__ __forceinline__ uint2 threefry2x32(uint32_t k0, uint32_t k1,
                                              uint32_t x0, uint32_t x1) {
    uint32_t ks0 = k0, ks1 = k1, ks2 = k0 ^ k1 ^ 0x1BD11BDAu;
    x0 += ks0; x1 += ks1;
#define TFR(r) { x0 += x1; x1 = (x1 << (r)) | (x1 >> (32 - (r))); x1 ^= x0; }
    TFR(13) TFR(15) TFR(26) TFR(6)
    x0 += ks1; x1 += ks2 + 1u;
    TFR(17) TFR(29) TFR(16) TFR(24)
    x0 += ks2; x1 += ks0 + 2u;
    TFR(13) TFR(15) TFR(26) TFR(6)
    x0 += ks0; x1 += ks1 + 3u;
    TFR(17) TFR(29) TFR(16) TFR(24)
    x0 += ks1; x1 += ks2 + 4u;
    TFR(13) TFR(15) TFR(26) TFR(6)
    x0 += ks2; x1 += ks0 + 5u;
#undef TFR
    return make_uint2(x0, x1);
}

// ---------------- k0: fold avgpool(2x2,*0.25) into conv weights ------------
__global__ void k_fold(const float* __restrict__ Win, const float* __restrict__ Wh1) {
    int i = blockIdx.x * blockDim.x + threadIdx.x;
    if (i < 3*36*32) {
        int oc = i & 31; int r = i >> 5; int uv = r % 36; int c = r / 36;
        int u = uv / 6, v = uv % 6;
        float s = 0.f;
        #pragma unroll
        for (int dh = 0; dh < 2; dh++)
            #pragma unroll
            for (int dw = 0; dw < 2; dw++) {
                int kh = u - dh, kw = v - dw;
                if (kh >= 0 && kh < 5 && kw >= 0 && kw < 5)
                    s += Win[(oc*3 + c)*25 + kh*5 + kw];
            }
        g_Wp1[i] = 0.25f * s;
    }
    if (i < 32*36*64) {
        int oc = i & 63; int r = i >> 6; int uv = r % 36; int c = r / 36;
        int u = uv / 6, v = uv % 6;
        float s = 0.f;
        #pragma unroll
        for (int dh = 0; dh < 2; dh++)
            #pragma unroll
            for (int dw = 0; dw < 2; dw++) {
                int kh = u - dh, kw = v - dw;
                if (kh >= 0 && kh < 5 && kw >= 0 && kw < 5)
                    s += Wh1[(oc*32 + c)*25 + kh*5 + kw];
            }
        g_Wp2[i] = 0.25f * s;
    }
}

// ---------------- k1: poisson spikes, ILP-4 --------------------------------
__global__ void k_spikes(const float* __restrict__ x) {
    int q = blockIdx.x * 256 + threadIdx.x;      // quad index < NSPK/4
    int i0 = q << 2;
    const float4 xv = *(const float4*)&x[i0 % XSZ];   // XSZ % 4 == 0: no wrap
    uint2 r0 = threefry2x32(0u, 1u, 0u, (uint32_t)(i0 + 0));
    uint2 r1 = threefry2x32(0u, 1u, 0u, (uint32_t)(i0 + 1));
    uint2 r2 = threefry2x32(0u, 1u, 0u, (uint32_t)(i0 + 2));
    uint2 r3 = threefry2x32(0u, 1u, 0u, (uint32_t)(i0 + 3));
    uchar4 o;
    float u;
    u = __uint_as_float(((r0.x ^ r0.y) >> 9) | 0x3f800000u) - 1.0f; o.x = (u < xv.x * 2.0f);
    u = __uint_as_float(((r1.x ^ r1.y) >> 9) | 0x3f800000u) - 1.0f; o.y = (u < xv.y * 2.0f);
    u = __uint_as_float(((r2.x ^ r2.y) >> 9) | 0x3f800000u) - 1.0f; o.z = (u < xv.z * 2.0f);
    u = __uint_as_float(((r3.x ^ r3.y) >> 9) | 0x3f800000u) - 1.0f; o.w = (u < xv.w * 2.0f);
    ((uchar4*)g_spk0)[q] = o;
}

// ---------------- k2: conv1+pool, worker = 4 sp x 16 oc --------------------
// 2 (t,b) tiles staged per block; 196 workers = (tile, oc-half, sp-quad).
// Per (c,u,v): 8 weight-ull (64B) + 4 inputs (16B) for 64 MACs = 1.25B/MAC.
__global__ __launch_bounds__(224) void k_conv1(void) {
    __shared__ float sIn[2][3*32*32];                 // 24KB
    __shared__ __align__(16) float sW[3*36*32];       // 13.5KB
    int tid = threadIdx.x;
    int tb0 = blockIdx.x * 2;

    #pragma unroll
    for (int tile = 0; tile < 2; tile++) {
        const uchar4* inp = (const uchar4*)(g_spk0 + (size_t)(tb0 + tile) * 3072);
        for (int i = tid; i < 768; i += 224) {
            uchar4 b4 = inp[i];
            *(float4*)&sIn[tile][i*4] =
                make_float4((float)b4.x, (float)b4.y, (float)b4.z, (float)b4.w);
        }
    }
    for (int i = tid; i < 3456; i += 224) sW[i] = g_Wp1[i];
    __syncthreads();
    if (tid >= 196) return;

    int tile = tid / 98;                  // 0..1
    int r    = tid - tile*98;
    int oh   = r / 49;                    // oc half: oc = oh*16 .. +15
    int q    = r - oh*49;                 // sp quad: sp = 4q .. 4q+3
    int sp0  = 4*q;
    int ia[4];
    #pragma unroll
    for (int s = 0; s < 4; s++) {
        int sp = sp0 + s;
        ia[s] = (sp/14)*64 + (sp%14)*2;   // (2ph)*32 + 2pw
    }
    const float* sIt = sIn[tile];

    ull acc[4][8];
    #pragma unroll
    for (int s = 0; s < 4; s++)
        #pragma unroll
        for (int j = 0; j < 8; j++) acc[s][j] = 0ull;

    #pragma unroll 1
    for (int c = 0; c < 3; c++) {
        const float* sIc = &sIt[c*1024];
        const float* wc  = &sW[c*1152 + oh*16];
        #pragma unroll 1
        for (int u = 0; u < 6; u++) {
            #pragma unroll
            for (int v = 0; v < 6; v++) {
                const ull* w = (const ull*)&wc[(u*6 + v)*32];
                ull w0 = w[0], w1 = w[1], w2 = w[2], w3 = w[3];
                ull w4 = w[4], w5 = w[5], w6 = w[6], w7 = w[7];
                #pragma unroll
                for (int s = 0; s < 4; s++) {
                    ull sa = pack_dup(sIc[ia[s] + u*32 + v]);
                    ffma2(acc[s][0], w0, sa); ffma2(acc[s][1], w1, sa);
                    ffma2(acc[s][2], w2, sa); ffma2(acc[s][3], w3, sa);
                    ffma2(acc[s][4], w4, sa); ffma2(acc[s][5], w5, sa);
                    ffma2(acc[s][6], w6, sa); ffma2(acc[s][7], w7, sa);
                }
            }
        }
    }
    int tb = tb0 + tile;
    #pragma unroll
    for (int s = 0; s < 4; s++) {
        ull* o = (ull*)&g_curin[(size_t)tb*6272 + (sp0 + s)*32 + oh*16];
        #pragma unroll
        for (int j = 0; j < 8; j++) o[j] = acc[s][j];
    }
}

// ---------------- k3: LIF scan layer 1 -> ballot bitmasks, MLP-8 -----------
__global__ void k_lif1(void) {
    int n = blockIdx.x*256 + threadIdx.x;       // < 401408 ; n = (b*196+sp)*32+oc
    int lane = threadIdx.x & 31;
    int bs = n >> 5;                            // b*196 + sp
    const float* cur = g_curin + n;
    unsigned* out = g_spk1 + bs;
    float spk = 0.f;
    #pragma unroll 1
    for (int t = 0; t < STEPS; t += 8) {
        float c[8]; unsigned m[8];
        #pragma unroll
        for (int k = 0; k < 8; k++) c[k] = cur[(size_t)(t+k)*N1];
        #pragma unroll
        for (int k = 0; k < 8; k++) {
            float mem = c[k] - spk;
            spk = (mem > 1.f) ? 1.f : 0.f;
            m[k] = __ballot_sync(0xffffffffu, mem > 1.f);
        }
        if (lane == 0) {
            #pragma unroll
            for (int k = 0; k < 8; k++) out[(size_t)(t+k)*12544] = m[k];
        }
    }
}

// ---------------- k4: conv2+pool, mask-windowed sparse, t-group of 4,
//                  TWO channels staged per sync ----------------------------
__global__ __launch_bounds__(256) void k_conv2(void) {
    __shared__ __align__(16) float sW[2*36*64]; // channels cc, cc+1 (18.4KB)
    __shared__ unsigned sMask4[4*196];          // oc-masks for 4 t
    __shared__ unsigned sRow[4][32*14];         // per-t per-channel row masks

    int tid = threadIdx.x;
    int b   = blockIdx.x & 63;
    int tg  = blockIdx.x >> 6;                  // 0..24
    int t0  = tg * 4;

    for (int i = tid; i < 4*196; i += 256) {
        int tt = i / 196, sp = i - tt*196;
        sMask4[i] = g_spk1[(size_t)(t0 + tt)*12544 + b*196 + sp];
    }
    __syncthreads();
    if (tid < 224) {                            // transpose to row bitmasks
        int c = tid & 31; int rp = tid >> 5;    // rp 0..6
        #pragma unroll
        for (int tt = 0; tt < 4; tt++) {
            const unsigned* mk = &sMask4[tt*196];
            #pragma unroll
            for (int rr = 0; rr < 2; rr++) {
                int ih = rp*2 + rr;
                unsigned m = 0;
                #pragma unroll
                for (int iw = 0; iw < 14; iw++)
                    m |= ((mk[ih*14 + iw] >> c) & 1u) << iw;
                sRow[tt][c*14 + ih] = m;
            }
        }
    }

    int active = (tid < 200);
    int sp = tid >> 3, og = tid & 7;            // sp 0..24, oc octet og*8..+7
    int ph = sp / 5, pw = sp % 5;
    int shift = 2*pw;
    ull acc[4][4];
    #pragma unroll
    for (int tt = 0; tt < 4; tt++)
        #pragma unroll
        for (int j = 0; j < 4; j++) acc[tt][j] = 0ull;

    #pragma unroll 1
    for (int cc = 0; cc < 32; cc += 2) {
        __syncthreads();                        // prev gather done (and transpose, 1st iter)
        for (int i = tid; i < 1152; i += 256)   // stage channels cc and cc+1
            *(float4*)&sW[i*4] = *(const float4*)&g_Wp2[cc*2304 + i*4];
        __syncthreads();
        #pragma unroll
        for (int half = 0; half < 2; half++) {  // c = cc, cc+1 (ascending: bit-exact)
            int c = cc + half;
            const float* wbuf = &sW[half*2304];
            if (active) {
                #pragma unroll
                for (int tt = 0; tt < 4; tt++) {
                    const unsigned* rc = &sRow[tt][c*14 + 2*ph];
                    #pragma unroll
                    for (int u = 0; u < 6; u++) {
                        unsigned bits = (rc[u] >> shift) & 63u;
                        while (bits) {
                            int v = __ffs(bits) - 1; bits &= bits - 1;
                            const ull* w = (const ull*)&wbuf[(u*6 + v)*64 + og*8];
                            fadd2(acc[tt][0], w[0]); fadd2(acc[tt][1], w[1]);
                            fadd2(acc[tt][2], w[2]); fadd2(acc[tt][3], w[3]);
                        }
                    }
                }
            }
        }
    }

    if (active) {
        #pragma unroll
        for (int tt = 0; tt < 4; tt++) {
            size_t ob = (size_t)((t0 + tt)*64 + b)*1600 + (size_t)(og*8)*25 + sp;
            float f[8];
            unpack2(acc[tt][0], f[0], f[1]); unpack2(acc[tt][1], f[2], f[3]);
            unpack2(acc[tt][2], f[4], f[5]); unpack2(acc[tt][3], f[6], f[7]);
            #pragma unroll
            for (int j = 0; j < 8; j++) g_curh1[ob + j*25] = f[j];
        }
    }
}

// ---------------- k5: LIF scan layer 2 (float4, unroll2) -------------------
__global__ void k_lif2(void) {
    int q = blockIdx.x*256 + threadIdx.x;       // < 25600 float4-neurons
    const float4* cur = (const float4*)g_curh1;
    uchar4* out = (uchar4*)g_spkh1;
    float s0 = 0.f, s1 = 0.f, s2 = 0.f, s3 = 0.f;
    #pragma unroll 1
    for (int t = 0; t < STEPS; t += 2) {
        float4 a = cur[(size_t)(t+0)*25600 + q];
        float4 b = cur[(size_t)(t+1)*25600 + q];
        float m; uchar4 o;
        m = a.x - s0; s0 = (m > 1.f) ? 1.f : 0.f; o.x = (unsigned char)(m > 1.f);
        m = a.y - s1; s1 = (m > 1.f) ? 1.f : 0.f; o.y = (unsigned char)(m > 1.f);
        m = a.z - s2; s2 = (m > 1.f) ? 1.f : 0.f; o.z = (unsigned char)(m > 1.f);
        m = a.w - s3; s3 = (m > 1.f) ? 1.f : 0.f; o.w = (unsigned char)(m > 1.f);
        out[(size_t)(t+0)*25600 + q] = o;
        m = b.x - s0; s0 = (m > 1.f) ? 1.f : 0.f; o.x = (unsigned char)(m > 1.f);
        m = b.y - s1; s1 = (m > 1.f) ? 1.f : 0.f; o.y = (unsigned char)(m > 1.f);
        m = b.z - s2; s2 = (m > 1.f) ? 1.f : 0.f; o.z = (unsigned char)(m > 1.f);
        m = b.w - s3; s3 = (m > 1.f) ? 1.f : 0.f; o.w = (unsigned char)(m > 1.f);
        out[(size_t)(t+1)*25600 + q] = o;
    }
}

// ---------------- k6: FC, 16 (t,b) pairs per block -------------------------
__global__ __launch_bounds__(320) void k_fc(const float* __restrict__ Wh2) {
    __shared__ unsigned char sS[16*1600];
    int tb0 = blockIdx.x * 16;
    int o = threadIdx.x >> 5, lane = threadIdx.x & 31;
    for (int i = threadIdx.x; i < 16*1600/16; i += 320)
        *(uint4*)&sS[i*16] = *(const uint4*)&g_spkh1[(size_t)tb0*1600 + i*16];
    __syncthreads();
    const float* w = Wh2 + o*1600;
    #pragma unroll 1
    for (int p = 0; p < 16; p++) {
        const unsigned char* s = &sS[p*1600];
        float acc = 0.f;
        for (int f = lane; f < 1600; f += 32) acc += (float)s[f] * w[f];
        #pragma unroll
        for (int off = 16; off; off >>= 1) acc += __shfl_down_sync(0xffffffffu, acc, off);
        if (lane == 0) g_fc[(tb0 + p)*10 + o] = acc;
    }
}

// ---------------- k7: output LIF scan + write spikes and mem ---------------
__global__ void k_lif3(float* __restrict__ out) {
    int i = blockIdx.x * blockDim.x + threadIdx.x;
    if (i >= BATCH*10) return;
    float spk = 0.f;
    for (int t = 0; t < STEPS; t++) {
        float mem = g_fc[t*640 + i] - spk;
        spk = (mem > 1.0f) ? 1.0f : 0.0f;
        out[t*640 + i] = spk;                    // out_spikes [100,64,10]
        out[STEPS*640 + t*640 + i] = mem;        // memh2      [100,64,10]
    }
}

// ---------------- launcher -------------------------------------------------
extern "C" void kernel_launch(void* const* d_in, const int* in_sizes, int n_in,
                              void* d_out, int out_size) {
    const float* x   = (const float*)d_in[0];   // [64,3,32,32]
    const float* Win = (const float*)d_in[1];   // [32,3,5,5]
    const float* Wh1 = (const float*)d_in[2];   // [64,32,5,5]
    const float* Wh2 = (const float*)d_in[3];   // [10,1600]
    float* out = (float*)d_out;

    k_fold  <<<288, 256>>>(Win, Wh1);
    k_spikes<<<NSPK/4/256, 256>>>(x);
    k_conv1 <<<TB/2, 224>>>();
    k_lif1  <<<N1/256, 256>>>();
    k_conv2 <<<1600, 256>>>();
    k_lif2  <<<N2/4/256, 256>>>();
    k_fc    <<<TB/16, 320>>>(Wh2);
    k_lif3  <<<3, 256>>>(out);
}

// round 12
// speedup vs baseline: 1.5687x; 1.0690x over previous
#include <cuda_runtime.h>
#include <cstdint>
#include <cstddef>

typedef unsigned long long ull;

// ---------------- problem constants ----------------
#define STEPS 100
#define BATCH 64
#define NSPK  (STEPS*BATCH*3*32*32)   // 19,660,800
#define XSZ   (BATCH*3*32*32)         // 196,608
#define N1    (BATCH*32*14*14)        // 401,408  (layer-1 neurons per step)
#define N2    (BATCH*64*5*5)          // 102,400  (layer-2 neurons per step)
#define TB    (STEPS*BATCH)           // 6400

// ---------------- scratch (device globals; no cudaMalloc allowed) ----------
__device__ __align__(16) unsigned char g_spk0[NSPK];          // poisson spikes [t][b][c][h][w]
__device__ __align__(16) float g_curin[(size_t)STEPS*N1];     // [t][b][sp196][oc32]
__device__ unsigned int  g_spk1[(size_t)STEPS*BATCH*196];     // [t][b*196+sp] -> 32-bit oc mask
__device__ __align__(16) float g_curh1[(size_t)STEPS*N2];     // [t][b][oc64*25+sp]
__device__ __align__(16) unsigned char g_spkh1[(size_t)STEPS*N2];
__device__ float         g_fc[STEPS*BATCH*10];
__device__ __align__(16) float g_Wp1[3*36*32];                // pooled conv1 W [c][uv6x6][oc32]
__device__ __align__(16) float g_Wp2[32*36*64];               // pooled conv2 W [c][uv6x6][oc64]

// ---------------- packed f32x2 helpers (bit-exact fp32 pairs) --------------
__device__ __forceinline__ void ffma2(ull& d, ull a, ull b) {
    asm("fma.rn.f32x2 %0, %1, %2, %0;" : "+l"(d) : "l"(a), "l"(b));
}
__device__ __forceinline__ void fadd2(ull& d, ull a) {
    asm("add.rn.f32x2 %0, %0, %1;" : "+l"(d) : "l"(a));
}
__device__ __forceinline__ ull pack_dup(float f) {
    ull p; asm("mov.b64 %0, {%1, %1};" : "=l"(p) : "f"(f)); return p;
}
__device__ __forceinline__ void unpack2(ull p, float& lo, float& hi) {
    asm("mov.b64 {%0, %1}, %2;" : "=f"(lo), "=f"(hi) : "l"(p));
}

// ---------------- threefry2x32 (JAX-exact, partitionable path) -------------
__device__ __forceinline__ uint2 threefry2x32(uint32_t k0, uint32_t k1,
                                              uint32_t x0, uint32_t x1) {
    uint32_t ks0 = k0, ks1 = k1, ks2 = k0 ^ k1 ^ 0x1BD11BDAu;
    x0 += ks0; x1 += ks1;
#define TFR(r) { x0 += x1; x1 = (x1 << (r)) | (x1 >> (32 - (r))); x1 ^= x0; }
    TFR(13) TFR(15) TFR(26) TFR(6)
    x0 += ks1; x1 += ks2 + 1u;
    TFR(17) TFR(29) TFR(16) TFR(24)
    x0 += ks2; x1 += ks0 + 2u;
    TFR(13) TFR(15) TFR(26) TFR(6)
    x0 += ks0; x1 += ks1 + 3u;
    TFR(17) TFR(29) TFR(16) TFR(24)
    x0 += ks1; x1 += ks2 + 4u;
    TFR(13) TFR(15) TFR(26) TFR(6)
    x0 += ks2; x1 += ks0 + 5u;
#undef TFR
    return make_uint2(x0, x1);
}

// ---------------- k0a/k0b: fold avgpool(2x2,*0.25) into conv weights -------
// (split into two launches so conv1 lands at launch index 3 for ncu capture)
__global__ void k_fold1(const float* __restrict__ Win) {
    int i = blockIdx.x * blockDim.x + threadIdx.x;
    if (i >= 3*36*32) return;
    int oc = i & 31; int r = i >> 5; int uv = r % 36; int c = r / 36;
    int u = uv / 6, v = uv % 6;
    float s = 0.f;
    #pragma unroll
    for (int dh = 0; dh < 2; dh++)
        #pragma unroll
        for (int dw = 0; dw < 2; dw++) {
            int kh = u - dh, kw = v - dw;
            if (kh >= 0 && kh < 5 && kw >= 0 && kw < 5)
                s += Win[(oc*3 + c)*25 + kh*5 + kw];
        }
    g_Wp1[i] = 0.25f * s;
}
__global__ void k_fold2(const float* __restrict__ Wh1) {
    int i = blockIdx.x * blockDim.x + threadIdx.x;
    if (i >= 32*36*64) return;
    int oc = i & 63; int r = i >> 6; int uv = r % 36; int c = r / 36;
    int u = uv / 6, v = uv % 6;
    float s = 0.f;
    #pragma unroll
    for (int dh = 0; dh < 2; dh++)
        #pragma unroll
        for (int dw = 0; dw < 2; dw++) {
            int kh = u - dh, kw = v - dw;
            if (kh >= 0 && kh < 5 && kw >= 0 && kw < 5)
                s += Wh1[(oc*32 + c)*25 + kh*5 + kw];
        }
    g_Wp2[i] = 0.25f * s;
}

// ---------------- k1: poisson spikes, ILP-4 --------------------------------
__global__ void k_spikes(const float* __restrict__ x) {
    int q = blockIdx.x * 256 + threadIdx.x;      // quad index < NSPK/4
    int i0 = q << 2;
    const float4 xv = *(const float4*)&x[i0 % XSZ];   // XSZ % 4 == 0: no wrap
    uint2 r0 = threefry2x32(0u, 1u, 0u, (uint32_t)(i0 + 0));
    uint2 r1 = threefry2x32(0u, 1u, 0u, (uint32_t)(i0 + 1));
    uint2 r2 = threefry2x32(0u, 1u, 0u, (uint32_t)(i0 + 2));
    uint2 r3 = threefry2x32(0u, 1u, 0u, (uint32_t)(i0 + 3));
    uchar4 o;
    float u;
    u = __uint_as_float(((r0.x ^ r0.y) >> 9) | 0x3f800000u) - 1.0f; o.x = (u < xv.x * 2.0f);
    u = __uint_as_float(((r1.x ^ r1.y) >> 9) | 0x3f800000u) - 1.0f; o.y = (u < xv.y * 2.0f);
    u = __uint_as_float(((r2.x ^ r2.y) >> 9) | 0x3f800000u) - 1.0f; o.z = (u < xv.z * 2.0f);
    u = __uint_as_float(((r3.x ^ r3.y) >> 9) | 0x3f800000u) - 1.0f; o.w = (u < xv.w * 2.0f);
    ((uchar4*)g_spk0)[q] = o;
}

// ---------------- k2: conv1+pool, worker = 4 sp x 16 oc --------------------
__global__ __launch_bounds__(224) void k_conv1(void) {
    __shared__ float sIn[2][3*32*32];                 // 24KB
    __shared__ __align__(16) float sW[3*36*32];       // 13.5KB
    int tid = threadIdx.x;
    int tb0 = blockIdx.x * 2;

    #pragma unroll
    for (int tile = 0; tile < 2; tile++) {
        const uchar4* inp = (const uchar4*)(g_spk0 + (size_t)(tb0 + tile) * 3072);
        for (int i = tid; i < 768; i += 224) {
            uchar4 b4 = inp[i];
            *(float4*)&sIn[tile][i*4] =
                make_float4((float)b4.x, (float)b4.y, (float)b4.z, (float)b4.w);
        }
    }
    for (int i = tid; i < 3456; i += 224) sW[i] = g_Wp1[i];
    __syncthreads();
    if (tid >= 196) return;

    int tile = tid / 98;                  // 0..1
    int r    = tid - tile*98;
    int oh   = r / 49;                    // oc half: oc = oh*16 .. +15
    int q    = r - oh*49;                 // sp quad: sp = 4q .. 4q+3
    int sp0  = 4*q;
    int ia[4];
    #pragma unroll
    for (int s = 0; s < 4; s++) {
        int sp = sp0 + s;
        ia[s] = (sp/14)*64 + (sp%14)*2;   // (2ph)*32 + 2pw
    }
    const float* sIt = sIn[tile];

    ull acc[4][8];
    #pragma unroll
    for (int s = 0; s < 4; s++)
        #pragma unroll
        for (int j = 0; j < 8; j++) acc[s][j] = 0ull;

    #pragma unroll 1
    for (int c = 0; c < 3; c++) {
        const float* sIc = &sIt[c*1024];
        const float* wc  = &sW[c*1152 + oh*16];
        #pragma unroll 1
        for (int u = 0; u < 6; u++) {
            #pragma unroll
            for (int v = 0; v < 6; v++) {
                const ull* w = (const ull*)&wc[(u*6 + v)*32];
                ull w0 = w[0], w1 = w[1], w2 = w[2], w3 = w[3];
                ull w4 = w[4], w5 = w[5], w6 = w[6], w7 = w[7];
                #pragma unroll
                for (int s = 0; s < 4; s++) {
                    ull sa = pack_dup(sIc[ia[s] + u*32 + v]);
                    ffma2(acc[s][0], w0, sa); ffma2(acc[s][1], w1, sa);
                    ffma2(acc[s][2], w2, sa); ffma2(acc[s][3], w3, sa);
                    ffma2(acc[s][4], w4, sa); ffma2(acc[s][5], w5, sa);
                    ffma2(acc[s][6], w6, sa); ffma2(acc[s][7], w7, sa);
                }
            }
        }
    }
    int tb = tb0 + tile;
    #pragma unroll
    for (int s = 0; s < 4; s++) {
        ull* o = (ull*)&g_curin[(size_t)tb*6272 + (sp0 + s)*32 + oh*16];
        #pragma unroll
        for (int j = 0; j < 8; j++) o[j] = acc[s][j];
    }
}

// ---------------- k3: LIF scan layer 1 -> ballot bitmasks, MLP-8 -----------
__global__ void k_lif1(void) {
    int n = blockIdx.x*256 + threadIdx.x;       // < 401408 ; n = (b*196+sp)*32+oc
    int lane = threadIdx.x & 31;
    int bs = n >> 5;                            // b*196 + sp
    const float* cur = g_curin + n;
    unsigned* out = g_spk1 + bs;
    float spk = 0.f;
    #pragma unroll 1
    for (int t = 0; t < STEPS; t += 8) {
        float c[8]; unsigned m[8];
        #pragma unroll
        for (int k = 0; k < 8; k++) c[k] = cur[(size_t)(t+k)*N1];
        #pragma unroll
        for (int k = 0; k < 8; k++) {
            float mem = c[k] - spk;
            spk = (mem > 1.f) ? 1.f : 0.f;
            m[k] = __ballot_sync(0xffffffffu, mem > 1.f);
        }
        if (lane == 0) {
            #pragma unroll
            for (int k = 0; k < 8; k++) out[(size_t)(t+k)*12544] = m[k];
        }
    }
}

// ---------------- k4: conv2+pool, divergent sparse gather over
//                  precomputed packed 36-bit windows ------------------------
__global__ __launch_bounds__(256) void k_conv2(void) {
    __shared__ __align__(16) float sW[2*36*64]; // channels cc, cc+1 (18.4KB)
    __shared__ unsigned sMask4[4*196];          // oc-masks for 4 t
    __shared__ unsigned sRow[4][32*14];         // per-t per-channel row masks
    __shared__ ull sWin[32*100];                // [c][tt*25+sp] packed windows

    int tid = threadIdx.x;
    int b   = blockIdx.x & 63;
    int tg  = blockIdx.x >> 6;                  // 0..24
    int t0  = tg * 4;

    for (int i = tid; i < 4*196; i += 256) {
        int tt = i / 196, sp = i - tt*196;
        sMask4[i] = g_spk1[(size_t)(t0 + tt)*12544 + b*196 + sp];
    }
    __syncthreads();
    for (int i = tid; i < 4*32*14; i += 256) {  // row bitmasks
        int ih = i % 14; int r = i / 14; int c = r & 31; int tt = r >> 5;
        const unsigned* mk = &sMask4[tt*196 + ih*14];
        unsigned m = 0;
        #pragma unroll
        for (int iw = 0; iw < 14; iw++) m |= ((mk[iw] >> c) & 1u) << iw;
        sRow[tt][c*14 + ih] = m;
    }
    __syncthreads();
    for (int i = tid; i < 32*100; i += 256) {   // packed 6x6 windows
        int c = i / 100; int r = i - c*100; int tt = r / 25; int sp = r - tt*25;
        int ph = sp / 5, pw = sp % 5;
        const unsigned* rc = &sRow[tt][c*14 + 2*ph];
        ull w = 0;
        #pragma unroll
        for (int u = 0; u < 6; u++)
            w |= (ull)((rc[u] >> (2*pw)) & 63u) << (6*u);
        sWin[c*100 + r] = w;
    }
    // first __syncthreads in the cc loop orders sWin build before gather

    int active = (tid < 200);
    int sp = tid >> 3, og = tid & 7;            // sp 0..24, oc octet og*8..+7
    ull acc[4][4];
    #pragma unroll
    for (int tt = 0; tt < 4; tt++)
        #pragma unroll
        for (int j = 0; j < 4; j++) acc[tt][j] = 0ull;

    #pragma unroll 1
    for (int cc = 0; cc < 32; cc += 2) {
        __syncthreads();                        // prev gather done (and sWin build, 1st iter)
        for (int i = tid; i < 1152; i += 256)   // stage channels cc and cc+1
            *(float4*)&sW[i*4] = *(const float4*)&g_Wp2[cc*2304 + i*4];
        __syncthreads();
        #pragma unroll
        for (int half = 0; half < 2; half++) {  // c = cc, cc+1 (ascending: bit-exact)
            int c = cc + half;
            const float* wbuf = &sW[half*2304];
            if (active) {
                #pragma unroll
                for (int tt = 0; tt < 4; tt++) {
                    ull bits = sWin[c*100 + tt*25 + sp];
                    while (bits) {
                        int idx = __ffsll((long long)bits) - 1;  // = u*6+v ascending
                        bits &= bits - 1;
                        const ull* w = (const ull*)&wbuf[idx*64 + og*8];
                        fadd2(acc[tt][0], w[0]); fadd2(acc[tt][1], w[1]);
                        fadd2(acc[tt][2], w[2]); fadd2(acc[tt][3], w[3]);
                    }
                }
            }
        }
    }

    if (active) {
        #pragma unroll
        for (int tt = 0; tt < 4; tt++) {
            size_t ob = (size_t)((t0 + tt)*64 + b)*1600 + (size_t)(og*8)*25 + sp;
            float f[8];
            unpack2(acc[tt][0], f[0], f[1]); unpack2(acc[tt][1], f[2], f[3]);
            unpack2(acc[tt][2], f[4], f[5]); unpack2(acc[tt][3], f[6], f[7]);
            #pragma unroll
            for (int j = 0; j < 8; j++) g_curh1[ob + j*25] = f[j];
        }
    }
}

// ---------------- k5: LIF scan layer 2 (float4, unroll2) -------------------
__global__ void k_lif2(void) {
    int q = blockIdx.x*256 + threadIdx.x;       // < 25600 float4-neurons
    const float4* cur = (const float4*)g_curh1;
    uchar4* out = (uchar4*)g_spkh1;
    float s0 = 0.f, s1 = 0.f, s2 = 0.f, s3 = 0.f;
    #pragma unroll 1
    for (int t = 0; t < STEPS; t += 2) {
        float4 a = cur[(size_t)(t+0)*25600 + q];
        float4 b = cur[(size_t)(t+1)*25600 + q];
        float m; uchar4 o;
        m = a.x - s0; s0 = (m > 1.f) ? 1.f : 0.f; o.x = (unsigned char)(m > 1.f);
        m = a.y - s1; s1 = (m > 1.f) ? 1.f : 0.f; o.y = (unsigned char)(m > 1.f);
        m = a.z - s2; s2 = (m > 1.f) ? 1.f : 0.f; o.z = (unsigned char)(m > 1.f);
        m = a.w - s3; s3 = (m > 1.f) ? 1.f : 0.f; o.w = (unsigned char)(m > 1.f);
        out[(size_t)(t+0)*25600 + q] = o;
        m = b.x - s0; s0 = (m > 1.f) ? 1.f : 0.f; o.x = (unsigned char)(m > 1.f);
        m = b.y - s1; s1 = (m > 1.f) ? 1.f : 0.f; o.y = (unsigned char)(m > 1.f);
        m = b.z - s2; s2 = (m > 1.f) ? 1.f : 0.f; o.z = (unsigned char)(m > 1.f);
        m = b.w - s3; s3 = (m > 1.f) ? 1.f : 0.f; o.w = (unsigned char)(m > 1.f);
        out[(size_t)(t+1)*25600 + q] = o;
    }
}

// ---------------- k6: FC, 16 (t,b) pairs per block -------------------------
__global__ __launch_bounds__(320) void k_fc(const float* __restrict__ Wh2) {
    __shared__ unsigned char sS[16*1600];
    int tb0 = blockIdx.x * 16;
    int o = threadIdx.x >> 5, lane = threadIdx.x & 31;
    for (int i = threadIdx.x; i < 16*1600/16; i += 320)
        *(uint4*)&sS[i*16] = *(const uint4*)&g_spkh1[(size_t)tb0*1600 + i*16];
    __syncthreads();
    const float* w = Wh2 + o*1600;
    #pragma unroll 1
    for (int p = 0; p < 16; p++) {
        const unsigned char* s = &sS[p*1600];
        float acc = 0.f;
        for (int f = lane; f < 1600; f += 32) acc += (float)s[f] * w[f];
        #pragma unroll
        for (int off = 16; off; off >>= 1) acc += __shfl_down_sync(0xffffffffu, acc, off);
        if (lane == 0) g_fc[(tb0 + p)*10 + o] = acc;
    }
}

// ---------------- k7: output LIF scan + write spikes and mem ---------------
__global__ void k_lif3(float* __restrict__ out) {
    int i = blockIdx.x * blockDim.x + threadIdx.x;
    if (i >= BATCH*10) return;
    float spk = 0.f;
    for (int t = 0; t < STEPS; t++) {
        float mem = g_fc[t*640 + i] - spk;
        spk = (mem > 1.0f) ? 1.0f : 0.0f;
        out[t*640 + i] = spk;                    // out_spikes [100,64,10]
        out[STEPS*640 + t*640 + i] = mem;        // memh2      [100,64,10]
    }
}

// ---------------- launcher -------------------------------------------------
extern "C" void kernel_launch(void* const* d_in, const int* in_sizes, int n_in,
                              void* d_out, int out_size) {
    const float* x   = (const float*)d_in[0];   // [64,3,32,32]
    const float* Win = (const float*)d_in[1];   // [32,3,5,5]
    const float* Wh1 = (const float*)d_in[2];   // [64,32,5,5]
    const float* Wh2 = (const float*)d_in[3];   // [10,1600]
    float* out = (float*)d_out;

    k_fold1 <<<14, 256>>>(Win);                 // idx 0
    k_fold2 <<<288, 256>>>(Wh1);                // idx 1
    k_spikes<<<NSPK/4/256, 256>>>(x);           // idx 2
    k_conv1 <<<TB/2, 224>>>();                  // idx 3  <- ncu capture lands here
    k_lif1  <<<N1/256, 256>>>();
    k_conv2 <<<1600, 256>>>();
    k_lif2  <<<N2/4/256, 256>>>();
    k_fc    <<<TB/16, 320>>>(Wh2);
    k_lif3  <<<3, 256>>>(out);
}

// round 13
// speedup vs baseline: 1.6531x; 1.0538x over previous
#include <cuda_runtime.h>
#include <cstdint>
#include <cstddef>

typedef unsigned long long ull;

// ---------------- problem constants ----------------
#define STEPS 100
#define BATCH 64
#define NSPK  (STEPS*BATCH*3*32*32)   // 19,660,800
#define XSZ   (BATCH*3*32*32)         // 196,608
#define N1    (BATCH*32*14*14)        // 401,408  (layer-1 neurons per step)
#define N2    (BATCH*64*5*5)          // 102,400  (layer-2 neurons per step)
#define TB    (STEPS*BATCH)           // 6400

// ---------------- scratch (device globals; no cudaMalloc allowed) ----------
__device__ __align__(16) unsigned char g_spk0[NSPK];          // poisson spikes [t][b][c][h][w]
__device__ __align__(16) float g_curin[(size_t)STEPS*N1];     // [t][b][sp196][oc32]
__device__ unsigned int  g_spk1[(size_t)STEPS*BATCH*196];     // [t][b*196+sp] -> 32-bit oc mask
__device__ __align__(16) float g_curh1[(size_t)STEPS*N2];     // [t][b][oc64*25+sp]
__device__ __align__(16) unsigned char g_spkh1[(size_t)STEPS*N2];
__device__ float         g_fc[STEPS*BATCH*10];
__device__ __align__(16) float g_Wp1[3*36*32];                // pooled conv1 W [c][uv6x6][oc32]
__device__ __align__(16) float g_Wp2[32*36*64];               // pooled conv2 W [c][uv6x6][oc64]

// ---------------- packed f32x2 helpers (bit-exact fp32 pairs) --------------
__device__ __forceinline__ void ffma2(ull& d, ull a, ull b) {
    asm("fma.rn.f32x2 %0, %1, %2, %0;" : "+l"(d) : "l"(a), "l"(b));
}
__device__ __forceinline__ void fadd2(ull& d, ull a) {
    asm("add.rn.f32x2 %0, %0, %1;" : "+l"(d) : "l"(a));
}
__device__ __forceinline__ ull pack_dup(float f) {
    ull p; asm("mov.b64 %0, {%1, %1};" : "=l"(p) : "f"(f)); return p;
}
__device__ __forceinline__ void unpack2(ull p, float& lo, float& hi) {
    asm("mov.b64 {%0, %1}, %2;" : "=f"(lo), "=f"(hi) : "l"(p));
}

// ---------------- threefry2x32 (JAX-exact, partitionable path) -------------
__device__ __forceinline__ uint2 threefry2x32(uint32_t k0, uint32_t k1,
                                              uint32_t x0, uint32_t x1) {
    uint32_t ks0 = k0, ks1 = k1, ks2 = k0 ^ k1 ^ 0x1BD11BDAu;
    x0 += ks0; x1 += ks1;
#define TFR(r) { x0 += x1; x1 = (x1 << (r)) | (x1 >> (32 - (r))); x1 ^= x0; }
    TFR(13) TFR(15) TFR(26) TFR(6)
    x0 += ks1; x1 += ks2 + 1u;
    TFR(17) TFR(29) TFR(16) TFR(24)
    x0 += ks2; x1 += ks0 + 2u;
    TFR(13) TFR(15) TFR(26) TFR(6)
    x0 += ks0; x1 += ks1 + 3u;
    TFR(17) TFR(29) TFR(16) TFR(24)
    x0 += ks1; x1 += ks2 + 4u;
    TFR(13) TFR(15) TFR(26) TFR(6)
    x0 += ks2; x1 += ks0 + 5u;
#undef TFR
    return make_uint2(x0, x1);
}

// ---------------- k0a/k0b: fold avgpool(2x2,*0.25) into conv weights -------
__global__ void k_fold1(const float* __restrict__ Win) {
    int i = blockIdx.x * blockDim.x + threadIdx.x;
    if (i >= 3*36*32) return;
    int oc = i & 31; int r = i >> 5; int uv = r % 36; int c = r / 36;
    int u = uv / 6, v = uv % 6;
    float s = 0.f;
    #pragma unroll
    for (int dh = 0; dh < 2; dh++)
        #pragma unroll
        for (int dw = 0; dw < 2; dw++) {
            int kh = u - dh, kw = v - dw;
            if (kh >= 0 && kh < 5 && kw >= 0 && kw < 5)
                s += Win[(oc*3 + c)*25 + kh*5 + kw];
        }
    g_Wp1[i] = 0.25f * s;
}
__global__ void k_fold2(const float* __restrict__ Wh1) {
    int i = blockIdx.x * blockDim.x + threadIdx.x;
    if (i >= 32*36*64) return;
    int oc = i & 63; int r = i >> 6; int uv = r % 36; int c = r / 36;
    int u = uv / 6, v = uv % 6;
    float s = 0.f;
    #pragma unroll
    for (int dh = 0; dh < 2; dh++)
        #pragma unroll
        for (int dw = 0; dw < 2; dw++) {
            int kh = u - dh, kw = v - dw;
            if (kh >= 0 && kh < 5 && kw >= 0 && kw < 5)
                s += Wh1[(oc*32 + c)*25 + kh*5 + kw];
        }
    g_Wp2[i] = 0.25f * s;
}

// ---------------- k1: poisson spikes, ILP-4 --------------------------------
__global__ void k_spikes(const float* __restrict__ x) {
    int q = blockIdx.x * 256 + threadIdx.x;      // quad index < NSPK/4
    int i0 = q << 2;
    const float4 xv = *(const float4*)&x[i0 % XSZ];   // XSZ % 4 == 0: no wrap
    uint2 r0 = threefry2x32(0u, 1u, 0u, (uint32_t)(i0 + 0));
    uint2 r1 = threefry2x32(0u, 1u, 0u, (uint32_t)(i0 + 1));
    uint2 r2 = threefry2x32(0u, 1u, 0u, (uint32_t)(i0 + 2));
    uint2 r3 = threefry2x32(0u, 1u, 0u, (uint32_t)(i0 + 3));
    uchar4 o;
    float u;
    u = __uint_as_float(((r0.x ^ r0.y) >> 9) | 0x3f800000u) - 1.0f; o.x = (u < xv.x * 2.0f);
    u = __uint_as_float(((r1.x ^ r1.y) >> 9) | 0x3f800000u) - 1.0f; o.y = (u < xv.y * 2.0f);
    u = __uint_as_float(((r2.x ^ r2.y) >> 9) | 0x3f800000u) - 1.0f; o.z = (u < xv.z * 2.0f);
    u = __uint_as_float(((r3.x ^ r3.y) >> 9) | 0x3f800000u) - 1.0f; o.w = (u < xv.w * 2.0f);
    ((uchar4*)g_spk0)[q] = o;
}

// ---------------- k2: conv1+pool, conflict-free float2 inputs --------------
// worker = 4 sp (q+49s) x 16 oc. Lanes = consecutive sp -> 8B stride LDS.64
// (dense, conflict-free). Inputs as float2 v-pairs; weights as LDS.128 bcast.
__global__ __launch_bounds__(224) void k_conv1(void) {
    __shared__ float sIn[2][3*32*32];                 // 24KB
    __shared__ __align__(16) float sW[3*36*32];       // 13.5KB
    int tid = threadIdx.x;
    int tb0 = blockIdx.x * 2;

    #pragma unroll
    for (int tile = 0; tile < 2; tile++) {
        const uchar4* inp = (const uchar4*)(g_spk0 + (size_t)(tb0 + tile) * 3072);
        for (int i = tid; i < 768; i += 224) {
            uchar4 b4 = inp[i];
            *(float4*)&sIn[tile][i*4] =
                make_float4((float)b4.x, (float)b4.y, (float)b4.z, (float)b4.w);
        }
    }
    for (int i = tid; i < 3456; i += 224) sW[i] = g_Wp1[i];
    __syncthreads();
    if (tid >= 196) return;

    int tile = tid / 98;                  // 0..1
    int r    = tid - tile*98;
    int oh   = r / 49;                    // oc half: oc = oh*16 .. +15
    int q    = r - oh*49;                 // worker sp set: q + 49*s, s=0..3
    int ia[4];
    #pragma unroll
    for (int s = 0; s < 4; s++) {
        int sp = q + 49*s;
        ia[s] = (sp/14)*64 + (sp%14)*2;   // (2ph)*32 + 2pw
    }
    const float* sIt = sIn[tile];

    ull acc[4][8];
    #pragma unroll
    for (int s = 0; s < 4; s++)
        #pragma unroll
        for (int j = 0; j < 8; j++) acc[s][j] = 0ull;

    #pragma unroll 1
    for (int c = 0; c < 3; c++) {
        const float* sIc = &sIt[c*1024];
        const float* wc  = &sW[c*1152 + oh*16];
        #pragma unroll 1
        for (int u = 0; u < 6; u++) {
            float2 in[4][3];              // cols {2pw+2k, 2pw+2k+1}, k=0..2
            #pragma unroll
            for (int s = 0; s < 4; s++)
                #pragma unroll
                for (int k = 0; k < 3; k++)
                    in[s][k] = *(const float2*)&sIc[ia[s] + u*32 + 2*k];
            #pragma unroll
            for (int v = 0; v < 6; v++) {
                const ulonglong2* w2 = (const ulonglong2*)&wc[(u*6 + v)*32];
                ulonglong2 wa = w2[0], wb = w2[1], wcc = w2[2], wd = w2[3];
                #pragma unroll
                for (int s = 0; s < 4; s++) {
                    float x = (v & 1) ? in[s][v >> 1].y : in[s][v >> 1].x;
                    ull sa = pack_dup(x);
                    ffma2(acc[s][0], wa.x, sa); ffma2(acc[s][1], wa.y, sa);
                    ffma2(acc[s][2], wb.x, sa); ffma2(acc[s][3], wb.y, sa);
                    ffma2(acc[s][4], wcc.x, sa); ffma2(acc[s][5], wcc.y, sa);
                    ffma2(acc[s][6], wd.x, sa); ffma2(acc[s][7], wd.y, sa);
                }
            }
        }
    }
    int tb = tb0 + tile;
    #pragma unroll
    for (int s = 0; s < 4; s++) {
        ull* o = (ull*)&g_curin[(size_t)tb*6272 + (q + 49*s)*32 + oh*16];
        #pragma unroll
        for (int j = 0; j < 8; j++) o[j] = acc[s][j];
    }
}

// ---------------- k3: LIF scan layer 1 -> ballot bitmasks, MLP-8 -----------
__global__ void k_lif1(void) {
    int n = blockIdx.x*256 + threadIdx.x;       // < 401408 ; n = (b*196+sp)*32+oc
    int lane = threadIdx.x & 31;
    int bs = n >> 5;                            // b*196 + sp
    const float* cur = g_curin + n;
    unsigned* out = g_spk1 + bs;
    float spk = 0.f;
    #pragma unroll 1
    for (int t = 0; t < STEPS; t += 8) {
        float c[8]; unsigned m[8];
        #pragma unroll
        for (int k = 0; k < 8; k++) c[k] = cur[(size_t)(t+k)*N1];
        #pragma unroll
        for (int k = 0; k < 8; k++) {
            float mem = c[k] - spk;
            spk = (mem > 1.f) ? 1.f : 0.f;
            m[k] = __ballot_sync(0xffffffffu, mem > 1.f);
        }
        if (lane == 0) {
            #pragma unroll
            for (int k = 0; k < 8; k++) out[(size_t)(t+k)*12544] = m[k];
        }
    }
}

// ---------------- k4: conv2+pool, divergent sparse gather over
//                  precomputed packed 36-bit windows ------------------------
__global__ __launch_bounds__(256) void k_conv2(void) {
    __shared__ __align__(16) float sW[2*36*64]; // channels cc, cc+1 (18.4KB)
    __shared__ unsigned sMask4[4*196];          // oc-masks for 4 t
    __shared__ unsigned sRow[4][32*14];         // per-t per-channel row masks
    __shared__ ull sWin[32*100];                // [c][tt*25+sp] packed windows

    int tid = threadIdx.x;
    int b   = blockIdx.x & 63;
    int tg  = blockIdx.x >> 6;                  // 0..24
    int t0  = tg * 4;

    for (int i = tid; i < 4*196; i += 256) {
        int tt = i / 196, sp = i - tt*196;
        sMask4[i] = g_spk1[(size_t)(t0 + tt)*12544 + b*196 + sp];
    }
    __syncthreads();
    for (int i = tid; i < 4*32*14; i += 256) {  // row bitmasks
        int ih = i % 14; int r = i / 14; int c = r & 31; int tt = r >> 5;
        const unsigned* mk = &sMask4[tt*196 + ih*14];
        unsigned m = 0;
        #pragma unroll
        for (int iw = 0; iw < 14; iw++) m |= ((mk[iw] >> c) & 1u) << iw;
        sRow[tt][c*14 + ih] = m;
    }
    __syncthreads();
    for (int i = tid; i < 32*100; i += 256) {   // packed 6x6 windows
        int c = i / 100; int r = i - c*100; int tt = r / 25; int sp = r - tt*25;
        int ph = sp / 5, pw = sp % 5;
        const unsigned* rc = &sRow[tt][c*14 + 2*ph];
        ull w = 0;
        #pragma unroll
        for (int u = 0; u < 6; u++)
            w |= (ull)((rc[u] >> (2*pw)) & 63u) << (6*u);
        sWin[c*100 + r] = w;
    }
    // first __syncthreads in the cc loop orders sWin build before gather

    int active = (tid < 200);
    int sp = tid >> 3, og = tid & 7;            // sp 0..24, oc octet og*8..+7
    ull acc[4][4];
    #pragma unroll
    for (int tt = 0; tt < 4; tt++)
        #pragma unroll
        for (int j = 0; j < 4; j++) acc[tt][j] = 0ull;

    #pragma unroll 1
    for (int cc = 0; cc < 32; cc += 2) {
        __syncthreads();                        // prev gather done (and sWin build, 1st iter)
        for (int i = tid; i < 1152; i += 256)   // stage channels cc and cc+1
            *(float4*)&sW[i*4] = *(const float4*)&g_Wp2[cc*2304 + i*4];
        __syncthreads();
        #pragma unroll
        for (int half = 0; half < 2; half++) {  // c = cc, cc+1 (ascending: bit-exact)
            int c = cc + half;
            const float* wbuf = &sW[half*2304];
            if (active) {
                #pragma unroll
                for (int tt = 0; tt < 4; tt++) {
                    ull bits = sWin[c*100 + tt*25 + sp];
                    while (bits) {
                        int idx = __ffsll((long long)bits) - 1;  // = u*6+v ascending
                        bits &= bits - 1;
                        const ull* w = (const ull*)&wbuf[idx*64 + og*8];
                        fadd2(acc[tt][0], w[0]); fadd2(acc[tt][1], w[1]);
                        fadd2(acc[tt][2], w[2]); fadd2(acc[tt][3], w[3]);
                    }
                }
            }
        }
    }

    if (active) {
        #pragma unroll
        for (int tt = 0; tt < 4; tt++) {
            size_t ob = (size_t)((t0 + tt)*64 + b)*1600 + (size_t)(og*8)*25 + sp;
            float f[8];
            unpack2(acc[tt][0], f[0], f[1]); unpack2(acc[tt][1], f[2], f[3]);
            unpack2(acc[tt][2], f[4], f[5]); unpack2(acc[tt][3], f[6], f[7]);
            #pragma unroll
            for (int j = 0; j < 8; j++) g_curh1[ob + j*25] = f[j];
        }
    }
}

// ---------------- k5: LIF scan layer 2 (float4, unroll2) -------------------
__global__ void k_lif2(void) {
    int q = blockIdx.x*256 + threadIdx.x;       // < 25600 float4-neurons
    const float4* cur = (const float4*)g_curh1;
    uchar4* out = (uchar4*)g_spkh1;
    float s0 = 0.f, s1 = 0.f, s2 = 0.f, s3 = 0.f;
    #pragma unroll 1
    for (int t = 0; t < STEPS; t += 2) {
        float4 a = cur[(size_t)(t+0)*25600 + q];
        float4 b = cur[(size_t)(t+1)*25600 + q];
        float m; uchar4 o;
        m = a.x - s0; s0 = (m > 1.f) ? 1.f : 0.f; o.x = (unsigned char)(m > 1.f);
        m = a.y - s1; s1 = (m > 1.f) ? 1.f : 0.f; o.y = (unsigned char)(m > 1.f);
        m = a.z - s2; s2 = (m > 1.f) ? 1.f : 0.f; o.z = (unsigned char)(m > 1.f);
        m = a.w - s3; s3 = (m > 1.f) ? 1.f : 0.f; o.w = (unsigned char)(m > 1.f);
        out[(size_t)(t+0)*25600 + q] = o;
        m = b.x - s0; s0 = (m > 1.f) ? 1.f : 0.f; o.x = (unsigned char)(m > 1.f);
        m = b.y - s1; s1 = (m > 1.f) ? 1.f : 0.f; o.y = (unsigned char)(m > 1.f);
        m = b.z - s2; s2 = (m > 1.f) ? 1.f : 0.f; o.z = (unsigned char)(m > 1.f);
        m = b.w - s3; s3 = (m > 1.f) ? 1.f : 0.f; o.w = (unsigned char)(m > 1.f);
        out[(size_t)(t+1)*25600 + q] = o;
    }
}

// ---------------- k6: FC, 16 (t,b) pairs per block -------------------------
__global__ __launch_bounds__(320) void k_fc(const float* __restrict__ Wh2) {
    __shared__ unsigned char sS[16*1600];
    int tb0 = blockIdx.x * 16;
    int o = threadIdx.x >> 5, lane = threadIdx.x & 31;
    for (int i = threadIdx.x; i < 16*1600/16; i += 320)
        *(uint4*)&sS[i*16] = *(const uint4*)&g_spkh1[(size_t)tb0*1600 + i*16];
    __syncthreads();
    const float* w = Wh2 + o*1600;
    #pragma unroll 1
    for (int p = 0; p < 16; p++) {
        const unsigned char* s = &sS[p*1600];
        float acc = 0.f;
        for (int f = lane; f < 1600; f += 32) acc += (float)s[f] * w[f];
        #pragma unroll
        for (int off = 16; off; off >>= 1) acc += __shfl_down_sync(0xffffffffu, acc, off);
        if (lane == 0) g_fc[(tb0 + p)*10 + o] = acc;
    }
}

// ---------------- k7: output LIF scan + write spikes and mem ---------------
__global__ void k_lif3(float* __restrict__ out) {
    int i = blockIdx.x * blockDim.x + threadIdx.x;
    if (i >= BATCH*10) return;
    float spk = 0.f;
    for (int t = 0; t < STEPS; t++) {
        float mem = g_fc[t*640 + i] - spk;
        spk = (mem > 1.0f) ? 1.0f : 0.0f;
        out[t*640 + i] = spk;                    // out_spikes [100,64,10]
        out[STEPS*640 + t*640 + i] = mem;        // memh2      [100,64,10]
    }
}

// ---------------- launcher -------------------------------------------------
extern "C" void kernel_launch(void* const* d_in, const int* in_sizes, int n_in,
                              void* d_out, int out_size) {
    const float* x   = (const float*)d_in[0];   // [64,3,32,32]
    const float* Win = (const float*)d_in[1];   // [32,3,5,5]
    const float* Wh1 = (const float*)d_in[2];   // [64,32,5,5]
    const float* Wh2 = (const float*)d_in[3];   // [10,1600]
    float* out = (float*)d_out;

    k_fold1 <<<14, 256>>>(Win);                 // idx 0
    k_fold2 <<<288, 256>>>(Wh1);                // idx 1
    k_spikes<<<NSPK/4/256, 256>>>(x);           // idx 2
    k_conv1 <<<TB/2, 224>>>();                  // idx 3  <- ncu capture lands here
    k_lif1  <<<N1/256, 256>>>();
    k_conv2 <<<1600, 256>>>();
    k_lif2  <<<N2/4/256, 256>>>();
    k_fc    <<<TB/16, 320>>>(Wh2);
    k_lif3  <<<3, 256>>>(out);
}

// round 14
// speedup vs baseline: 1.6637x; 1.0064x over previous
#include <cuda_runtime.h>
#include <cstdint>
#include <cstddef>

typedef unsigned long long ull;

// ---------------- problem constants ----------------
#define STEPS 100
#define BATCH 64
#define NSPK  (STEPS*BATCH*3*32*32)   // 19,660,800
#define XSZ   (BATCH*3*32*32)         // 196,608
#define N1    (BATCH*32*14*14)        // 401,408  (layer-1 neurons per step)
#define N2    (BATCH*64*5*5)          // 102,400  (layer-2 neurons per step)
#define TB    (STEPS*BATCH)           // 6400

// ---------------- scratch (device globals; no cudaMalloc allowed) ----------
__device__ __align__(16) unsigned char g_spk0[NSPK];          // poisson spikes [t][b][c][h][w]
__device__ __align__(16) float g_curin[(size_t)STEPS*N1];     // [t][b][sp196][oc32]
__device__ unsigned int  g_spk1[(size_t)STEPS*BATCH*196];     // [t][b*196+sp] -> 32-bit oc mask
__device__ __align__(16) float g_curh1[(size_t)STEPS*N2];     // [t][b][oc64*25+sp]
__device__ __align__(16) unsigned char g_spkh1[(size_t)STEPS*N2];
__device__ float         g_fc[STEPS*BATCH*10];
__device__ __align__(16) float g_Wp1[3*36*32];                // pooled conv1 W [c][uv6x6][oc32]
__device__ __align__(16) float g_Wp2[32*36*64];               // pooled conv2 W [c][uv6x6][oc64]

// ---------------- packed f32x2 helpers (bit-exact fp32 pairs) --------------
__device__ __forceinline__ void ffma2(ull& d, ull a, ull b) {
    asm("fma.rn.f32x2 %0, %1, %2, %0;" : "+l"(d) : "l"(a), "l"(b));
}
__device__ __forceinline__ void fadd2(ull& d, ull a) {
    asm("add.rn.f32x2 %0, %0, %1;" : "+l"(d) : "l"(a));
}
__device__ __forceinline__ ull pack_dup(float f) {
    ull p; asm("mov.b64 %0, {%1, %1};" : "=l"(p) : "f"(f)); return p;
}
__device__ __forceinline__ void unpack2(ull p, float& lo, float& hi) {
    asm("mov.b64 {%0, %1}, %2;" : "=f"(lo), "=f"(hi) : "l"(p));
}

// ---------------- threefry2x32 (JAX-exact, partitionable path) -------------
__device__ __forceinline__ uint2 threefry2x32(uint32_t k0, uint32_t k1,
                                              uint32_t x0, uint32_t x1) {
    uint32_t ks0 = k0, ks1 = k1, ks2 = k0 ^ k1 ^ 0x1BD11BDAu;
    x0 += ks0; x1 += ks1;
#define TFR(r) { x0 += x1; x1 = (x1 << (r)) | (x1 >> (32 - (r))); x1 ^= x0; }
    TFR(13) TFR(15) TFR(26) TFR(6)
    x0 += ks1; x1 += ks2 + 1u;
    TFR(17) TFR(29) TFR(16) TFR(24)
    x0 += ks2; x1 += ks0 + 2u;
    TFR(13) TFR(15) TFR(26) TFR(6)
    x0 += ks0; x1 += ks1 + 3u;
    TFR(17) TFR(29) TFR(16) TFR(24)
    x0 += ks1; x1 += ks2 + 4u;
    TFR(13) TFR(15) TFR(26) TFR(6)
    x0 += ks2; x1 += ks0 + 5u;
#undef TFR
    return make_uint2(x0, x1);
}

// ---------------- k0a/k0b: fold avgpool(2x2,*0.25) into conv weights -------
__global__ void k_fold1(const float* __restrict__ Win) {
    int i = blockIdx.x * blockDim.x + threadIdx.x;
    if (i >= 3*36*32) return;
    int oc = i & 31; int r = i >> 5; int uv = r % 36; int c = r / 36;
    int u = uv / 6, v = uv % 6;
    float s = 0.f;
    #pragma unroll
    for (int dh = 0; dh < 2; dh++)
        #pragma unroll
        for (int dw = 0; dw < 2; dw++) {
            int kh = u - dh, kw = v - dw;
            if (kh >= 0 && kh < 5 && kw >= 0 && kw < 5)
                s += Win[(oc*3 + c)*25 + kh*5 + kw];
        }
    g_Wp1[i] = 0.25f * s;
}
__global__ void k_fold2(const float* __restrict__ Wh1) {
    int i = blockIdx.x * blockDim.x + threadIdx.x;
    if (i >= 32*36*64) return;
    int oc = i & 63; int r = i >> 6; int uv = r % 36; int c = r / 36;
    int u = uv / 6, v = uv % 6;
    float s = 0.f;
    #pragma unroll
    for (int dh = 0; dh < 2; dh++)
        #pragma unroll
        for (int dw = 0; dw < 2; dw++) {
            int kh = u - dh, kw = v - dw;
            if (kh >= 0 && kh < 5 && kw >= 0 && kw < 5)
                s += Wh1[(oc*32 + c)*25 + kh*5 + kw];
        }
    g_Wp2[i] = 0.25f * s;
}

// ---------------- k1: poisson spikes, ILP-4 --------------------------------
__global__ void k_spikes(const float* __restrict__ x) {
    int q = blockIdx.x * 256 + threadIdx.x;      // quad index < NSPK/4
    int i0 = q << 2;
    const float4 xv = *(const float4*)&x[i0 % XSZ];   // XSZ % 4 == 0: no wrap
    uint2 r0 = threefry2x32(0u, 1u, 0u, (uint32_t)(i0 + 0));
    uint2 r1 = threefry2x32(0u, 1u, 0u, (uint32_t)(i0 + 1));
    uint2 r2 = threefry2x32(0u, 1u, 0u, (uint32_t)(i0 + 2));
    uint2 r3 = threefry2x32(0u, 1u, 0u, (uint32_t)(i0 + 3));
    uchar4 o;
    float u;
    u = __uint_as_float(((r0.x ^ r0.y) >> 9) | 0x3f800000u) - 1.0f; o.x = (u < xv.x * 2.0f);
    u = __uint_as_float(((r1.x ^ r1.y) >> 9) | 0x3f800000u) - 1.0f; o.y = (u < xv.y * 2.0f);
    u = __uint_as_float(((r2.x ^ r2.y) >> 9) | 0x3f800000u) - 1.0f; o.z = (u < xv.z * 2.0f);
    u = __uint_as_float(((r3.x ^ r3.y) >> 9) | 0x3f800000u) - 1.0f; o.w = (u < xv.w * 2.0f);
    ((uchar4*)g_spk0)[q] = o;
}

// ---------------- k2: conv1+pool, worker = 2 sp x 16 oc (occupancy) --------
// block = one (t,b) tile, 256 threads, 196 workers = (oh, sp-pair {q, q+98}).
// Lanes = consecutive sp -> dense conflict-free float2 input loads.
__global__ __launch_bounds__(256) void k_conv1(void) {
    __shared__ float sIn[3*32*32];                    // 12KB
    __shared__ __align__(16) float sW[3*36*32];       // 13.5KB
    int tid = threadIdx.x;
    int tb  = blockIdx.x;

    {
        const uchar4* inp = (const uchar4*)(g_spk0 + (size_t)tb * 3072);
        for (int i = tid; i < 768; i += 256) {
            uchar4 b4 = inp[i];
            *(float4*)&sIn[i*4] =
                make_float4((float)b4.x, (float)b4.y, (float)b4.z, (float)b4.w);
        }
    }
    for (int i = tid; i < 3456; i += 256) sW[i] = g_Wp1[i];
    __syncthreads();
    if (tid >= 196) return;

    int oh = tid / 98;                    // oc half: oc = oh*16 .. +15
    int q  = tid - oh*98;                 // sp pair: {q, q+98}
    int ia[2];
    #pragma unroll
    for (int s = 0; s < 2; s++) {
        int sp = q + 98*s;
        ia[s] = (sp/14)*64 + (sp%14)*2;   // (2ph)*32 + 2pw
    }

    ull acc[2][8];
    #pragma unroll
    for (int s = 0; s < 2; s++)
        #pragma unroll
        for (int j = 0; j < 8; j++) acc[s][j] = 0ull;

    #pragma unroll 1
    for (int c = 0; c < 3; c++) {
        const float* sIc = &sIn[c*1024];
        const float* wc  = &sW[c*1152 + oh*16];
        #pragma unroll 1
        for (int u = 0; u < 6; u++) {
            float2 in[2][3];              // cols {2pw+2k, 2pw+2k+1}, k=0..2
            #pragma unroll
            for (int s = 0; s < 2; s++)
                #pragma unroll
                for (int k = 0; k < 3; k++)
                    in[s][k] = *(const float2*)&sIc[ia[s] + u*32 + 2*k];
            #pragma unroll
            for (int v = 0; v < 6; v++) {
                const ulonglong2* w2 = (const ulonglong2*)&wc[(u*6 + v)*32];
                ulonglong2 wa = w2[0], wb = w2[1], wcc = w2[2], wd = w2[3];
                #pragma unroll
                for (int s = 0; s < 2; s++) {
                    float x = (v & 1) ? in[s][v >> 1].y : in[s][v >> 1].x;
                    ull sa = pack_dup(x);
                    ffma2(acc[s][0], wa.x, sa); ffma2(acc[s][1], wa.y, sa);
                    ffma2(acc[s][2], wb.x, sa); ffma2(acc[s][3], wb.y, sa);
                    ffma2(acc[s][4], wcc.x, sa); ffma2(acc[s][5], wcc.y, sa);
                    ffma2(acc[s][6], wd.x, sa); ffma2(acc[s][7], wd.y, sa);
                }
            }
        }
    }
    #pragma unroll
    for (int s = 0; s < 2; s++) {
        ull* o = (ull*)&g_curin[(size_t)tb*6272 + (q + 98*s)*32 + oh*16];
        #pragma unroll
        for (int j = 0; j < 8; j++) o[j] = acc[s][j];
    }
}

// ---------------- k3: LIF scan layer 1 -> ballot bitmasks, MLP-8 -----------
__global__ void k_lif1(void) {
    int n = blockIdx.x*256 + threadIdx.x;       // < 401408 ; n = (b*196+sp)*32+oc
    int lane = threadIdx.x & 31;
    int bs = n >> 5;                            // b*196 + sp
    const float* cur = g_curin + n;
    unsigned* out = g_spk1 + bs;
    float spk = 0.f;
    #pragma unroll 1
    for (int t = 0; t < STEPS; t += 8) {
        float c[8]; unsigned m[8];
        #pragma unroll
        for (int k = 0; k < 8; k++) c[k] = cur[(size_t)(t+k)*N1];
        #pragma unroll
        for (int k = 0; k < 8; k++) {
            float mem = c[k] - spk;
            spk = (mem > 1.f) ? 1.f : 0.f;
            m[k] = __ballot_sync(0xffffffffu, mem > 1.f);
        }
        if (lane == 0) {
            #pragma unroll
            for (int k = 0; k < 8; k++) out[(size_t)(t+k)*12544] = m[k];
        }
    }
}

// ---------------- k4: conv2+pool, divergent sparse gather over
//                  precomputed packed 36-bit windows, LDS.128 ---------------
__global__ __launch_bounds__(256) void k_conv2(void) {
    __shared__ __align__(16) float sW[2*36*64]; // channels cc, cc+1 (18.4KB)
    __shared__ unsigned sMask4[4*196];          // oc-masks for 4 t
    __shared__ unsigned sRow[4][32*14];         // per-t per-channel row masks
    __shared__ ull sWin[32*100];                // [c][tt*25+sp] packed windows

    int tid = threadIdx.x;
    int b   = blockIdx.x & 63;
    int tg  = blockIdx.x >> 6;                  // 0..24
    int t0  = tg * 4;

    for (int i = tid; i < 4*196; i += 256) {
        int tt = i / 196, sp = i - tt*196;
        sMask4[i] = g_spk1[(size_t)(t0 + tt)*12544 + b*196 + sp];
    }
    __syncthreads();
    for (int i = tid; i < 4*32*14; i += 256) {  // row bitmasks
        int ih = i % 14; int r = i / 14; int c = r & 31; int tt = r >> 5;
        const unsigned* mk = &sMask4[tt*196 + ih*14];
        unsigned m = 0;
        #pragma unroll
        for (int iw = 0; iw < 14; iw++) m |= ((mk[iw] >> c) & 1u) << iw;
        sRow[tt][c*14 + ih] = m;
    }
    __syncthreads();
    for (int i = tid; i < 32*100; i += 256) {   // packed 6x6 windows
        int c = i / 100; int r = i - c*100; int tt = r / 25; int sp = r - tt*25;
        int ph = sp / 5, pw = sp % 5;
        const unsigned* rc = &sRow[tt][c*14 + 2*ph];
        ull w = 0;
        #pragma unroll
        for (int u = 0; u < 6; u++)
            w |= (ull)((rc[u] >> (2*pw)) & 63u) << (6*u);
        sWin[c*100 + r] = w;
    }
    // first __syncthreads in the cc loop orders sWin build before gather

    int active = (tid < 200);
    int sp = tid >> 3, og = tid & 7;            // sp 0..24, oc octet og*8..+7
    ull acc[4][4];
    #pragma unroll
    for (int tt = 0; tt < 4; tt++)
        #pragma unroll
        for (int j = 0; j < 4; j++) acc[tt][j] = 0ull;

    #pragma unroll 1
    for (int cc = 0; cc < 32; cc += 2) {
        __syncthreads();                        // prev gather done (and sWin build, 1st iter)
        for (int i = tid; i < 1152; i += 256)   // stage channels cc and cc+1
            *(float4*)&sW[i*4] = *(const float4*)&g_Wp2[cc*2304 + i*4];
        __syncthreads();
        #pragma unroll
        for (int half = 0; half < 2; half++) {  // c = cc, cc+1 (ascending: bit-exact)
            int c = cc + half;
            const float* wbuf = &sW[half*2304];
            if (active) {
                #pragma unroll
                for (int tt = 0; tt < 4; tt++) {
                    ull bits = sWin[c*100 + tt*25 + sp];
                    while (bits) {
                        int idx = __ffsll((long long)bits) - 1;  // = u*6+v ascending
                        bits &= bits - 1;
                        const ulonglong2* w = (const ulonglong2*)&wbuf[idx*64 + og*8];
                        ulonglong2 wa = w[0], wb = w[1];
                        fadd2(acc[tt][0], wa.x); fadd2(acc[tt][1], wa.y);
                        fadd2(acc[tt][2], wb.x); fadd2(acc[tt][3], wb.y);
                    }
                }
            }
        }
    }

    if (active) {
        #pragma unroll
        for (int tt = 0; tt < 4; tt++) {
            size_t ob = (size_t)((t0 + tt)*64 + b)*1600 + (size_t)(og*8)*25 + sp;
            float f[8];
            unpack2(acc[tt][0], f[0], f[1]); unpack2(acc[tt][1], f[2], f[3]);
            unpack2(acc[tt][2], f[4], f[5]); unpack2(acc[tt][3], f[6], f[7]);
            #pragma unroll
            for (int j = 0; j < 8; j++) g_curh1[ob + j*25] = f[j];
        }
    }
}

// ---------------- k5: LIF scan layer 2 (float4, unroll2) -------------------
__global__ void k_lif2(void) {
    int q = blockIdx.x*256 + threadIdx.x;       // < 25600 float4-neurons
    const float4* cur = (const float4*)g_curh1;
    uchar4* out = (uchar4*)g_spkh1;
    float s0 = 0.f, s1 = 0.f, s2 = 0.f, s3 = 0.f;
    #pragma unroll 1
    for (int t = 0; t < STEPS; t += 2) {
        float4 a = cur[(size_t)(t+0)*25600 + q];
        float4 b = cur[(size_t)(t+1)*25600 + q];
        float m; uchar4 o;
        m = a.x - s0; s0 = (m > 1.f) ? 1.f : 0.f; o.x = (unsigned char)(m > 1.f);
        m = a.y - s1; s1 = (m > 1.f) ? 1.f : 0.f; o.y = (unsigned char)(m > 1.f);
        m = a.z - s2; s2 = (m > 1.f) ? 1.f : 0.f; o.z = (unsigned char)(m > 1.f);
        m = a.w - s3; s3 = (m > 1.f) ? 1.f : 0.f; o.w = (unsigned char)(m > 1.f);
        out[(size_t)(t+0)*25600 + q] = o;
        m = b.x - s0; s0 = (m > 1.f) ? 1.f : 0.f; o.x = (unsigned char)(m > 1.f);
        m = b.y - s1; s1 = (m > 1.f) ? 1.f : 0.f; o.y = (unsigned char)(m > 1.f);
        m = b.z - s2; s2 = (m > 1.f) ? 1.f : 0.f; o.z = (unsigned char)(m > 1.f);
        m = b.w - s3; s3 = (m > 1.f) ? 1.f : 0.f; o.w = (unsigned char)(m > 1.f);
        out[(size_t)(t+1)*25600 + q] = o;
    }
}

// ---------------- k6: FC, 16 (t,b) pairs per block -------------------------
__global__ __launch_bounds__(320) void k_fc(const float* __restrict__ Wh2) {
    __shared__ unsigned char sS[16*1600];
    int tb0 = blockIdx.x * 16;
    int o = threadIdx.x >> 5, lane = threadIdx.x & 31;
    for (int i = threadIdx.x; i < 16*1600/16; i += 320)
        *(uint4*)&sS[i*16] = *(const uint4*)&g_spkh1[(size_t)tb0*1600 + i*16];
    __syncthreads();
    const float* w = Wh2 + o*1600;
    #pragma unroll 1
    for (int p = 0; p < 16; p++) {
        const unsigned char* s = &sS[p*1600];
        float acc = 0.f;
        for (int f = lane; f < 1600; f += 32) acc += (float)s[f] * w[f];
        #pragma unroll
        for (int off = 16; off; off >>= 1) acc += __shfl_down_sync(0xffffffffu, acc, off);
        if (lane == 0) g_fc[(tb0 + p)*10 + o] = acc;
    }
}

// ---------------- k7: output LIF scan + write spikes and mem ---------------
__global__ void k_lif3(float* __restrict__ out) {
    int i = blockIdx.x * blockDim.x + threadIdx.x;
    if (i >= BATCH*10) return;
    float spk = 0.f;
    for (int t = 0; t < STEPS; t++) {
        float mem = g_fc[t*640 + i] - spk;
        spk = (mem > 1.0f) ? 1.0f : 0.0f;
        out[t*640 + i] = spk;                    // out_spikes [100,64,10]
        out[STEPS*640 + t*640 + i] = mem;        // memh2      [100,64,10]
    }
}

// ---------------- launcher -------------------------------------------------
extern "C" void kernel_launch(void* const* d_in, const int* in_sizes, int n_in,
                              void* d_out, int out_size) {
    const float* x   = (const float*)d_in[0];   // [64,3,32,32]
    const float* Win = (const float*)d_in[1];   // [32,3,5,5]
    const float* Wh1 = (const float*)d_in[2];   // [64,32,5,5]
    const float* Wh2 = (const float*)d_in[3];   // [10,1600]
    float* out = (float*)d_out;

    k_fold1 <<<14, 256>>>(Win);                 // idx 0
    k_fold2 <<<288, 256>>>(Wh1);                // idx 1
    k_spikes<<<NSPK/4/256, 256>>>(x);           // idx 2
    k_conv1 <<<TB, 256>>>();                    // idx 3  <- ncu capture lands here
    k_lif1  <<<N1/256, 256>>>();
    k_conv2 <<<1600, 256>>>();
    k_lif2  <<<N2/4/256, 256>>>();
    k_fc    <<<TB/16, 320>>>(Wh2);
    k_lif3  <<<3, 256>>>(out);
}